// round 9
// baseline (speedup 1.0000x reference)
#include <cuda_runtime.h>
#include <math.h>
#include <stdint.h>

// Problem constants
#define BB      16
#define LL      2048
#define DD      768
#define HH      12
#define NLAYER  4
#define FDIM    32
#define HDIM    64
#define NTOK    (BB * LL)            // 32768
#define ATTN_EPS 1e-6f
#define LN_EPS   1e-5f
#define NBH     (BB * HH)            // 192
#define KVCH    4                    // kv L-split chunks

// ---------------------------------------------------------------------------
// Scratch buffers
// ---------------------------------------------------------------------------
__device__ float g_X [(size_t)NTOK * DD];
__device__ float g_Y [(size_t)NTOK * DD];
__device__ float g_Q [(size_t)NTOK * DD];
__device__ float g_K [(size_t)NTOK * DD];
__device__ float g_V [(size_t)NTOK * DD];
__device__ float g_PHQ[(size_t)NTOK * HH * FDIM];
__device__ float g_PHK[(size_t)NTOK * HH * FDIM];
__device__ float g_KV  [NBH * FDIM * HDIM];
__device__ float g_KSUM[NBH * FDIM];
__device__ float g_KVP [KVCH * NBH * FDIM * HDIM];
__device__ float g_KSP [KVCH * NBH * FDIM];
__device__ float g_COS [LL * (HDIM / 2)];
__device__ float g_SIN [LL * (HDIM / 2)];

// ---------------------------------------------------------------------------
// PTX helpers
// ---------------------------------------------------------------------------
__device__ __forceinline__ void cpa16(uint32_t d, const void* s) {
    asm volatile("cp.async.cg.shared.global [%0], [%1], 16;" :: "r"(d), "l"(s));
}
#define CPA_COMMIT() asm volatile("cp.async.commit_group;" ::: "memory")
#define CPA_WAIT1()  asm volatile("cp.async.wait_group 1;" ::: "memory")

__device__ __forceinline__ uint32_t smem_u32(const void* p) {
    uint32_t a;
    asm("{ .reg .u64 t; cvta.to.shared.u64 t, %1; cvt.u32.u64 %0, t; }"
        : "=r"(a) : "l"(p));
    return a;
}

__device__ __forceinline__ void mma_tf32(float* c, const unsigned* a,
                                         unsigned b0, unsigned b1) {
    asm volatile(
        "mma.sync.aligned.m16n8k8.row.col.f32.tf32.tf32.f32 "
        "{%0,%1,%2,%3},{%4,%5,%6,%7},{%8,%9},{%0,%1,%2,%3};"
        : "+f"(c[0]), "+f"(c[1]), "+f"(c[2]), "+f"(c[3])
        : "r"(a[0]), "r"(a[1]), "r"(a[2]), "r"(a[3]), "r"(b0), "r"(b1));
}

// ---------------------------------------------------------------------------
// Pipelined tf32 GEMM: C[32768,768] = act(A @ W + bias) (+R)
// CTA tile 128x256x32, 8 warps of 64x64 (FM=4, FN=8), cp.async 3-stage.
// Inner loop keeps only 2 live B-frag registers.
// ---------------------------------------------------------------------------
#define TM 128
#define TN 256
#define TBK 32
#define NST 3
#define A_STR 36
#define B_STR 264
#define A_TILE_B (TM * A_STR * 4)           // 18432
#define B_TILE_B (TBK * B_STR * 4)          // 33792
#define STAGE_B  (A_TILE_B + B_TILE_B)      // 52224
#define OFF_BIAS (NST * STAGE_B)            // 156672
#define SMEM_GEMM (OFF_BIAS + TN * 4)       // 157696
#define NKT (DD / TBK)                      // 24

__global__ __launch_bounds__(256, 1) void pgemm_kernel(
    const float* __restrict__ A, const float* __restrict__ W,
    const float* __restrict__ bias, const float* __restrict__ R,
    float* __restrict__ C, int act)
{
    extern __shared__ char smem[];
    uint32_t sb = smem_u32(smem);
    int tid = threadIdx.x, lane = tid & 31, warp = tid >> 5;
    int wm = (warp & 1) * 64;
    int wn = (warp >> 1) * 64;
    size_t row0 = (size_t)blockIdx.y * TM;
    size_t col0 = (size_t)blockIdx.x * TN;

    *(float*)(smem + OFF_BIAS + tid * 4) = bias[col0 + tid];

    int ar = tid >> 3, akc = tid & 7;          // A loads: 4 per thread
    int bk = tid >> 5, bnc = tid & 31;         // B loads: 8 per thread
    auto load_stage = [&](int u) {
        uint32_t st = sb + (u % NST) * STAGE_B;
        int k0 = u * TBK;
        #pragma unroll
        for (int i = 0; i < 4; i++) {
            int r = ar + i * 32;
            cpa16(st + r * (A_STR * 4) + akc * 16,
                  A + (row0 + r) * DD + k0 + akc * 4);
        }
        uint32_t bbase = st + A_TILE_B;
        #pragma unroll
        for (int i = 0; i < 4; i++) {
            int k = bk + i * 8;
            #pragma unroll
            for (int j = 0; j < 2; j++) {
                int nc = bnc + j * 32;
                cpa16(bbase + k * (B_STR * 4) + nc * 16,
                      W + (size_t)(k0 + k) * DD + col0 + nc * 4);
            }
        }
    };

    float acc[4][8][4];
    #pragma unroll
    for (int i = 0; i < 4; i++)
        #pragma unroll
        for (int j = 0; j < 8; j++)
            #pragma unroll
            for (int k = 0; k < 4; k++) acc[i][j][k] = 0.f;

    load_stage(0); CPA_COMMIT();
    load_stage(1); CPA_COMMIT();

    for (int t = 0; t < NKT; t++) {
        CPA_WAIT1();
        __syncthreads();
        if (t + 2 < NKT) load_stage(t + 2);
        CPA_COMMIT();
        const float* sA = (const float*)(smem + (t % NST) * STAGE_B);
        const float* sB = (const float*)(smem + (t % NST) * STAGE_B + A_TILE_B);
        #pragma unroll
        for (int ks = 0; ks < 4; ks++) {
            int kc = ks * 8 + (lane & 3);
            unsigned a[4][4];
            #pragma unroll
            for (int fm = 0; fm < 4; fm++) {
                int r = wm + fm * 16 + (lane >> 2);
                a[fm][0] = __float_as_uint(sA[r * A_STR + kc]);
                a[fm][1] = __float_as_uint(sA[(r + 8) * A_STR + kc]);
                a[fm][2] = __float_as_uint(sA[r * A_STR + kc + 4]);
                a[fm][3] = __float_as_uint(sA[(r + 8) * A_STR + kc + 4]);
            }
            #pragma unroll
            for (int fn = 0; fn < 8; fn++) {
                int cn = wn + fn * 8 + (lane >> 2);
                unsigned b0 = __float_as_uint(sB[kc * B_STR + cn]);
                unsigned b1 = __float_as_uint(sB[(kc + 4) * B_STR + cn]);
                #pragma unroll
                for (int fm = 0; fm < 4; fm++)
                    mma_tf32(acc[fm][fn], a[fm], b0, b1);
            }
        }
    }

    // epilogue
    const float* sbias = (const float*)(smem + OFF_BIAS);
    #pragma unroll
    for (int fm = 0; fm < 4; fm++) {
        size_t r0 = row0 + wm + fm * 16 + (lane >> 2);
        size_t r1 = r0 + 8;
        #pragma unroll
        for (int fn = 0; fn < 8; fn++) {
            int cl = wn + fn * 8 + 2 * (lane & 3);
            size_t cn = col0 + cl;
            float bx = sbias[cl], by = sbias[cl + 1];
            float v0 = acc[fm][fn][0] + bx;
            float v1 = acc[fm][fn][1] + by;
            float v2 = acc[fm][fn][2] + bx;
            float v3 = acc[fm][fn][3] + by;
            if (act == 1) {
                v0 = 0.5f * v0 * (1.f + erff(v0 * 0.70710678118654752f));
                v1 = 0.5f * v1 * (1.f + erff(v1 * 0.70710678118654752f));
                v2 = 0.5f * v2 * (1.f + erff(v2 * 0.70710678118654752f));
                v3 = 0.5f * v3 * (1.f + erff(v3 * 0.70710678118654752f));
            }
            if (R) {
                float2 ra = *(const float2*)(R + r0 * DD + cn);
                float2 rb = *(const float2*)(R + r1 * DD + cn);
                v0 += ra.x; v1 += ra.y; v2 += rb.x; v3 += rb.y;
            }
            *(float2*)(C + r0 * DD + cn) = make_float2(v0, v1);
            *(float2*)(C + r1 * DD + cn) = make_float2(v2, v3);
        }
    }
}

// ---------------------------------------------------------------------------
// Embedding gather
// ---------------------------------------------------------------------------
__global__ __launch_bounds__(256) void embed_kernel(
    const int* __restrict__ idx, const float* __restrict__ emb,
    float* __restrict__ X)
{
    int i   = blockIdx.x * 256 + threadIdx.x;
    int tok = i / (DD / 4);
    int c4  = i % (DD / 4);
    const float4* src = (const float4*)(emb + (size_t)idx[tok] * DD);
    ((float4*)X)[i] = src[c4];
}

// ---------------------------------------------------------------------------
// Rotary cos/sin table
// ---------------------------------------------------------------------------
__global__ __launch_bounds__(256) void rope_table_kernel(
    float* __restrict__ cosT, float* __restrict__ sinT)
{
    int i = blockIdx.x * 256 + threadIdx.x;
    int j = i & 31;
    int l = i >> 5;
    double inv = pow(10000.0, -(double)(2 * j) / (double)HDIM);
    double fr  = (double)l * inv;
    cosT[i] = (float)cos(fr);
    sinT[i] = (float)sin(fr);
}

// ---------------------------------------------------------------------------
// Fused rotary + feature map (proven no-spill, one matrix per launch)
// ---------------------------------------------------------------------------
__global__ __launch_bounds__(256) void phi_rot_kernel(
    const float* __restrict__ X, const float* __restrict__ omega,
    const float* __restrict__ cosT, const float* __restrict__ sinT,
    const int* __restrict__ mask, float* __restrict__ PH)
{
    __shared__ float4 som[HDIM * FDIM / 4];
    int tid = threadIdx.x;
    #pragma unroll
    for (int p = 0; p < 2; p++)
        som[tid + p * 256] = ((const float4*)omega)[tid + p * 256];
    __syncthreads();

    int id = blockIdx.x * 256 + tid;
    int n  = id / HH;
    int h  = id % HH;
    int l  = n & (LL - 1);

    float q[HDIM];
    const float4* src = (const float4*)(X + (size_t)n * DD + h * HDIM);
    #pragma unroll
    for (int i = 0; i < HDIM / 4; i++) {
        float4 v = src[i];
        q[i * 4 + 0] = v.x; q[i * 4 + 1] = v.y;
        q[i * 4 + 2] = v.z; q[i * 4 + 3] = v.w;
    }
    #pragma unroll
    for (int j = 0; j < 32; j++) {
        float c = cosT[l * 32 + j];
        float s = sinT[l * 32 + j];
        float x1 = q[j], x2 = q[j + 32];
        q[j]      = x1 * c - x2 * s;
        q[j + 32] = x2 * c + x1 * s;
    }
    float m = mask ? (float)mask[n] : 1.0f;

    float4* out = (float4*)(PH + (size_t)id * FDIM);
    #pragma unroll
    for (int f4 = 0; f4 < FDIM / 4; f4++) {
        float4 acc = make_float4(0.f, 0.f, 0.f, 0.f);
        #pragma unroll
        for (int d = 0; d < HDIM; d++) {
            float4 w = som[d * 8 + f4];
            acc.x += q[d] * w.x; acc.y += q[d] * w.y;
            acc.z += q[d] * w.z; acc.w += q[d] * w.w;
        }
        acc.x = fmaxf(acc.x, 0.f) * m; acc.y = fmaxf(acc.y, 0.f) * m;
        acc.z = fmaxf(acc.z, 0.f) * m; acc.w = fmaxf(acc.w, 0.f) * m;
        out[f4] = acc;
    }
}

// ---------------------------------------------------------------------------
// KV partial reduction: 4 L-chunks per (b,h), deterministic partial buffers
// ---------------------------------------------------------------------------
__global__ __launch_bounds__(256) void kv_part_kernel(
    const float* __restrict__ PHK, const float* __restrict__ V,
    float* __restrict__ KVP, float* __restrict__ KSP)
{
    __shared__ float sph[32 * FDIM];
    __shared__ float sv [32 * HDIM];
    int bh = blockIdx.x;
    int ch = blockIdx.y;
    int b  = bh / HH;
    int h  = bh % HH;
    int tid = threadIdx.x;
    int f  = tid & 31;
    int dg = tid >> 5;
    float acc[8] = {0.f,0.f,0.f,0.f,0.f,0.f,0.f,0.f};
    float sacc = 0.f;

    int rA  = tid >> 3, cA = (tid & 7) * 4;
    int lbeg = ch * (LL / KVCH), lend = lbeg + LL / KVCH;
    for (int l0 = lbeg; l0 < lend; l0 += 32) {
        *(float4*)&sph[rA * FDIM + cA] =
            *(const float4*)(PHK + ((size_t)(b * LL + l0 + rA) * HH + h) * FDIM + cA);
        #pragma unroll
        for (int p = 0; p < 2; p++) {
            int ii = tid + p * 256;
            int rr = ii >> 4, cc = (ii & 15) * 4;
            *(float4*)&sv[rr * HDIM + cc] =
                *(const float4*)(V + (size_t)(b * LL + l0 + rr) * DD + h * HDIM + cc);
        }
        __syncthreads();
        #pragma unroll 8
        for (int r = 0; r < 32; r++) {
            float ph = sph[r * FDIM + f];
            sacc += ph;
            float4 v0 = *(const float4*)&sv[r * HDIM + dg * 8];
            float4 v1 = *(const float4*)&sv[r * HDIM + dg * 8 + 4];
            acc[0] += ph * v0.x; acc[1] += ph * v0.y;
            acc[2] += ph * v0.z; acc[3] += ph * v0.w;
            acc[4] += ph * v1.x; acc[5] += ph * v1.y;
            acc[6] += ph * v1.z; acc[7] += ph * v1.w;
        }
        __syncthreads();
    }
    float* dst = KVP + (((size_t)ch * NBH + bh) * FDIM + f) * HDIM + dg * 8;
    #pragma unroll
    for (int jj = 0; jj < 8; jj++) dst[jj] = acc[jj];
    if (dg == 0) KSP[((size_t)ch * NBH + bh) * FDIM + f] = sacc;
}

__global__ __launch_bounds__(256) void kv_reduce_kernel(
    const float* __restrict__ KVP, const float* __restrict__ KSP,
    float* __restrict__ KV, float* __restrict__ KSUM)
{
    int i = blockIdx.x * 256 + threadIdx.x;
    const int NKV = NBH * FDIM * HDIM;   // 393216
    if (i < NKV) {
        float s = KVP[i] + KVP[NKV + i] + KVP[2 * NKV + i] + KVP[3 * NKV + i];
        KV[i] = s;
    }
    if (i < NBH * FDIM) {
        const int NS = NBH * FDIM;
        KSUM[i] = KSP[i] + KSP[NS + i] + KSP[2 * NS + i] + KSP[3 * NS + i];
    }
}

// ---------------------------------------------------------------------------
// Attention output
// ---------------------------------------------------------------------------
__global__ __launch_bounds__(256) void attn_out_kernel(
    const float* __restrict__ PHQ, const float* __restrict__ KV,
    const float* __restrict__ KSUM, float* __restrict__ Y)
{
    __shared__ float4 skv[FDIM * HDIM / 4];
    __shared__ float  sks[FDIM];
    int bh  = blockIdx.y;
    int tid = threadIdx.x;
    #pragma unroll
    for (int p = 0; p < 2; p++)
        skv[tid + p * 256] = ((const float4*)(KV + (size_t)bh * FDIM * HDIM))[tid + p * 256];
    if (tid < FDIM) sks[tid] = KSUM[bh * FDIM + tid];
    __syncthreads();

    int b = bh / HH, h = bh % HH;
    size_t n = (size_t)b * LL + blockIdx.x * 256 + tid;

    float ph[FDIM];
    const float4* src = (const float4*)(PHQ + (n * HH + h) * FDIM);
    #pragma unroll
    for (int i = 0; i < FDIM / 4; i++) {
        float4 v = src[i];
        ph[i * 4 + 0] = v.x; ph[i * 4 + 1] = v.y;
        ph[i * 4 + 2] = v.z; ph[i * 4 + 3] = v.w;
    }
    float den = ATTN_EPS;
    #pragma unroll
    for (int fI = 0; fI < FDIM; fI++) den += ph[fI] * sks[fI];
    float z = 1.0f / den;

    float4* outp = (float4*)(Y + n * DD + h * HDIM);
    #pragma unroll
    for (int d4 = 0; d4 < HDIM / 4; d4++) {
        float4 acc = make_float4(0.f, 0.f, 0.f, 0.f);
        #pragma unroll
        for (int fI = 0; fI < FDIM; fI++) {
            float4 kvv = skv[fI * 16 + d4];
            acc.x += ph[fI] * kvv.x; acc.y += ph[fI] * kvv.y;
            acc.z += ph[fI] * kvv.z; acc.w += ph[fI] * kvv.w;
        }
        acc.x *= z; acc.y *= z; acc.z *= z; acc.w *= z;
        outp[d4] = acc;
    }
}

// ---------------------------------------------------------------------------
// One-pass LayerNorm: 192 threads, float4, warp-shuffle reduce
// ---------------------------------------------------------------------------
__global__ __launch_bounds__(192) void ln_kernel(
    const float* __restrict__ in, const float* __restrict__ g,
    const float* __restrict__ b, float* __restrict__ out)
{
    __shared__ float ws[6], ws2[6], smv[2];
    size_t row = blockIdx.x;
    int tid = threadIdx.x;
    int lane = tid & 31, wid = tid >> 5;

    float4 v = ((const float4*)(in + row * DD))[tid];
    float s  = v.x + v.y + v.z + v.w;
    float s2 = v.x * v.x + v.y * v.y + v.z * v.z + v.w * v.w;
    #pragma unroll
    for (int off = 16; off > 0; off >>= 1) {
        s  += __shfl_xor_sync(0xFFFFFFFF, s,  off);
        s2 += __shfl_xor_sync(0xFFFFFFFF, s2, off);
    }
    if (lane == 0) { ws[wid] = s; ws2[wid] = s2; }
    __syncthreads();
    if (tid < 32) {
        float a  = (lane < 6) ? ws[lane]  : 0.f;
        float a2 = (lane < 6) ? ws2[lane] : 0.f;
        #pragma unroll
        for (int off = 4; off > 0; off >>= 1) {
            a  += __shfl_xor_sync(0xFFFFFFFF, a,  off);
            a2 += __shfl_xor_sync(0xFFFFFFFF, a2, off);
        }
        if (lane == 0) {
            float mu = a * (1.0f / DD);
            smv[0] = mu;
            smv[1] = rsqrtf(a2 * (1.0f / DD) - mu * mu + LN_EPS);
        }
    }
    __syncthreads();
    float mu = smv[0], rstd = smv[1];
    float4 gg = ((const float4*)g)[tid];
    float4 bb = ((const float4*)b)[tid];
    float4 o;
    o.x = (v.x - mu) * rstd * gg.x + bb.x;
    o.y = (v.y - mu) * rstd * gg.y + bb.y;
    o.z = (v.z - mu) * rstd * gg.z + bb.z;
    o.w = (v.w - mu) * rstd * gg.w + bb.w;
    ((float4*)(out + row * DD))[tid] = o;
}

// ---------------------------------------------------------------------------
// Host orchestration
// ---------------------------------------------------------------------------
extern "C" void kernel_launch(void* const* d_in, const int* in_sizes, int n_in,
                              void* d_out, int out_size)
{
    const int*   idx     = (const int*)  d_in[0];
    const int*   mask    = (const int*)  d_in[1];
    const float* tok_emb = (const float*)d_in[2];
    const float* Wq = (const float*)d_in[3];
    const float* bq = (const float*)d_in[4];
    const float* Wk = (const float*)d_in[5];
    const float* bk = (const float*)d_in[6];
    const float* Wv = (const float*)d_in[7];
    const float* bv = (const float*)d_in[8];
    const float* Wo = (const float*)d_in[9];
    const float* bo = (const float*)d_in[10];
    const float* om = (const float*)d_in[11];
    const float* W1 = (const float*)d_in[12];
    const float* b1 = (const float*)d_in[13];
    const float* W2 = (const float*)d_in[14];
    const float* b2 = (const float*)d_in[15];
    const float* g1 = (const float*)d_in[16];
    const float* be1= (const float*)d_in[17];
    const float* g2 = (const float*)d_in[18];
    const float* be2= (const float*)d_in[19];
    const float* gf = (const float*)d_in[20];
    const float* bf = (const float*)d_in[21];
    float* out = (float*)d_out;

    float *X, *Y, *Q, *K, *V, *PHQ, *PHK, *KV, *KSUM, *KVP, *KSP, *COS, *SIN;
    cudaGetSymbolAddress((void**)&X,    g_X);
    cudaGetSymbolAddress((void**)&Y,    g_Y);
    cudaGetSymbolAddress((void**)&Q,    g_Q);
    cudaGetSymbolAddress((void**)&K,    g_K);
    cudaGetSymbolAddress((void**)&V,    g_V);
    cudaGetSymbolAddress((void**)&PHQ,  g_PHQ);
    cudaGetSymbolAddress((void**)&PHK,  g_PHK);
    cudaGetSymbolAddress((void**)&KV,   g_KV);
    cudaGetSymbolAddress((void**)&KSUM, g_KSUM);
    cudaGetSymbolAddress((void**)&KVP,  g_KVP);
    cudaGetSymbolAddress((void**)&KSP,  g_KSP);
    cudaGetSymbolAddress((void**)&COS,  g_COS);
    cudaGetSymbolAddress((void**)&SIN,  g_SIN);

    cudaFuncSetAttribute(pgemm_kernel,
                         cudaFuncAttributeMaxDynamicSharedMemorySize, SMEM_GEMM);

    const size_t WMAT = (size_t)DD * DD;
    dim3 gGrid(DD / TN, NTOK / TM);   // (3, 256)

    rope_table_kernel<<<(LL * 32) / 256, 256>>>(COS, SIN);
    embed_kernel<<<(NTOK * DD / 4) / 256, 256>>>(idx, tok_emb, X);

    for (int i = 0; i < NLAYER; i++) {
        const float* om_i = om + (size_t)i * HDIM * FDIM;

        pgemm_kernel<<<gGrid, 256, SMEM_GEMM>>>(X, Wq + i * WMAT, bq + i * DD, nullptr, Q, 0);
        pgemm_kernel<<<gGrid, 256, SMEM_GEMM>>>(X, Wk + i * WMAT, bk + i * DD, nullptr, K, 0);
        pgemm_kernel<<<gGrid, 256, SMEM_GEMM>>>(X, Wv + i * WMAT, bv + i * DD, nullptr, V, 0);

        phi_rot_kernel<<<(NTOK * HH) / 256, 256>>>(Q, om_i, COS, SIN, nullptr, PHQ);
        phi_rot_kernel<<<(NTOK * HH) / 256, 256>>>(K, om_i, COS, SIN, mask,    PHK);

        kv_part_kernel<<<dim3(NBH, KVCH), 256>>>(PHK, V, KVP, KSP);
        kv_reduce_kernel<<<(NBH * FDIM * HDIM) / 256, 256>>>(KVP, KSP, KV, KSUM);

        attn_out_kernel<<<dim3(LL / 256, NBH), 256>>>(PHQ, KV, KSUM, Y);

        // X = Y @ Wo + bo + X
        pgemm_kernel<<<gGrid, 256, SMEM_GEMM>>>(Y, Wo + i * WMAT, bo + i * DD, X, X, 0);
        ln_kernel<<<NTOK, 192>>>(X, g1 + i * DD, be1 + i * DD, X);
        // Q = gelu(X @ W1 + b1)
        pgemm_kernel<<<gGrid, 256, SMEM_GEMM>>>(X, W1 + i * WMAT, b1 + i * DD, nullptr, Q, 1);
        // Y = Q @ W2 + b2 + X
        pgemm_kernel<<<gGrid, 256, SMEM_GEMM>>>(Q, W2 + i * WMAT, b2 + i * DD, X, Y, 0);
        ln_kernel<<<NTOK, 192>>>(Y, g2 + i * DD, be2 + i * DD, X);
    }

    ln_kernel<<<NTOK, 192>>>(X, gf, bf, out);
}

// round 10
// speedup vs baseline: 1.0796x; 1.0796x over previous
#include <cuda_runtime.h>
#include <math.h>
#include <stdint.h>

// Problem constants
#define BB      16
#define LL      2048
#define DD      768
#define HH      12
#define NLAYER  4
#define FDIM    32
#define HDIM    64
#define NTOK    (BB * LL)            // 32768
#define ATTN_EPS 1e-6f
#define LN_EPS   1e-5f
#define NBH     (BB * HH)            // 192
#define KVCH    4                    // kv L-split chunks

// ---------------------------------------------------------------------------
// Scratch buffers
// ---------------------------------------------------------------------------
__device__ float g_X [(size_t)NTOK * DD];
__device__ float g_Y [(size_t)NTOK * DD];
__device__ float g_Q [(size_t)NTOK * DD];
__device__ float g_K [(size_t)NTOK * DD];
__device__ float g_V [(size_t)NTOK * DD];
__device__ float g_PHQ[(size_t)NTOK * HH * FDIM];
__device__ float g_PHK[(size_t)NTOK * HH * FDIM];
__device__ float g_KV  [NBH * FDIM * HDIM];
__device__ float g_KSUM[NBH * FDIM];
__device__ float g_KVP [KVCH * NBH * FDIM * HDIM];
__device__ float g_KSP [KVCH * NBH * FDIM];
__device__ float g_COS [LL * (HDIM / 2)];
__device__ float g_SIN [LL * (HDIM / 2)];

// ---------------------------------------------------------------------------
// PTX helpers
// ---------------------------------------------------------------------------
__device__ __forceinline__ void cpa16(uint32_t d, const void* s) {
    asm volatile("cp.async.cg.shared.global [%0], [%1], 16;" :: "r"(d), "l"(s));
}
#define CPA_COMMIT() asm volatile("cp.async.commit_group;" ::: "memory")
#define CPA_WAIT1()  asm volatile("cp.async.wait_group 1;" ::: "memory")

__device__ __forceinline__ uint32_t smem_u32(const void* p) {
    uint32_t a;
    asm("{ .reg .u64 t; cvta.to.shared.u64 t, %1; cvt.u32.u64 %0, t; }"
        : "=r"(a) : "l"(p));
    return a;
}

__device__ __forceinline__ void mma_tf32(float* c, const unsigned* a, const unsigned* b) {
    asm volatile(
        "mma.sync.aligned.m16n8k8.row.col.f32.tf32.tf32.f32 "
        "{%0,%1,%2,%3},{%4,%5,%6,%7},{%8,%9},{%0,%1,%2,%3};"
        : "+f"(c[0]), "+f"(c[1]), "+f"(c[2]), "+f"(c[3])
        : "r"(a[0]), "r"(a[1]), "r"(a[2]), "r"(a[3]), "r"(b[0]), "r"(b[1]));
}

// ---------------------------------------------------------------------------
// GEMM body (R4-proven shape): 128x128x32 tile, 8 warps of 64x32,
// cp.async 3-stage. Shared by pgemm_kernel and qkv_gemm_kernel.
// ---------------------------------------------------------------------------
#define TM 128
#define TN 128
#define TBK 32
#define NST 3
#define A_STR 36
#define B_STR 136
#define A_TILE_B (TM * A_STR * 4)           // 18432
#define B_TILE_B (TBK * B_STR * 4)          // 17408
#define STAGE_B  (A_TILE_B + B_TILE_B)      // 35840
#define OFF_BIAS (NST * STAGE_B)            // 107520
#define SMEM_GEMM (OFF_BIAS + TN * 4)       // 108032
#define NKT (DD / TBK)                      // 24

__device__ __forceinline__ void gemm_body(
    const float* __restrict__ A, const float* __restrict__ W,
    const float* __restrict__ bias, const float* __restrict__ R,
    float* __restrict__ C, int act, size_t row0, size_t col0, char* smem)
{
    uint32_t sb = smem_u32(smem);
    int tid = threadIdx.x, lane = tid & 31, warp = tid >> 5;
    int wm = (warp & 1) * 64;
    int wn = (warp >> 1) * 32;

    if (tid < TN) *(float*)(smem + OFF_BIAS + tid * 4) = bias[col0 + tid];

    int ar = tid >> 3, akc = tid & 7;
    int bk = tid >> 5, bnc = tid & 31;
    auto load_stage = [&](int u) {
        uint32_t st = sb + (u % NST) * STAGE_B;
        int k0 = u * TBK;
        #pragma unroll
        for (int i = 0; i < 4; i++) {
            int r = ar + i * 32;
            cpa16(st + r * (A_STR * 4) + akc * 16,
                  A + (row0 + r) * DD + k0 + akc * 4);
        }
        uint32_t bbase = st + A_TILE_B;
        #pragma unroll
        for (int i = 0; i < 4; i++) {
            int k = bk + i * 8;
            cpa16(bbase + k * (B_STR * 4) + bnc * 16,
                  W + (size_t)(k0 + k) * DD + col0 + bnc * 4);
        }
    };

    float acc[4][4][4];
    #pragma unroll
    for (int i = 0; i < 4; i++)
        #pragma unroll
        for (int j = 0; j < 4; j++)
            #pragma unroll
            for (int k = 0; k < 4; k++) acc[i][j][k] = 0.f;

    load_stage(0); CPA_COMMIT();
    load_stage(1); CPA_COMMIT();

    for (int t = 0; t < NKT; t++) {
        CPA_WAIT1();
        __syncthreads();
        if (t + 2 < NKT) load_stage(t + 2);
        CPA_COMMIT();
        const float* sA = (const float*)(smem + (t % NST) * STAGE_B);
        const float* sB = (const float*)(smem + (t % NST) * STAGE_B + A_TILE_B);
        #pragma unroll
        for (int ks = 0; ks < 4; ks++) {
            int kc = ks * 8 + (lane & 3);
            unsigned a[4][4], b[4][2];
            #pragma unroll
            for (int fm = 0; fm < 4; fm++) {
                int r = wm + fm * 16 + (lane >> 2);
                a[fm][0] = __float_as_uint(sA[r * A_STR + kc]);
                a[fm][1] = __float_as_uint(sA[(r + 8) * A_STR + kc]);
                a[fm][2] = __float_as_uint(sA[r * A_STR + kc + 4]);
                a[fm][3] = __float_as_uint(sA[(r + 8) * A_STR + kc + 4]);
            }
            #pragma unroll
            for (int fn = 0; fn < 4; fn++) {
                int cn = wn + fn * 8 + (lane >> 2);
                b[fn][0] = __float_as_uint(sB[kc * B_STR + cn]);
                b[fn][1] = __float_as_uint(sB[(kc + 4) * B_STR + cn]);
            }
            #pragma unroll
            for (int fm = 0; fm < 4; fm++)
                #pragma unroll
                for (int fn = 0; fn < 4; fn++)
                    mma_tf32(acc[fm][fn], a[fm], b[fn]);
        }
    }

    const float* sbias = (const float*)(smem + OFF_BIAS);
    #pragma unroll
    for (int fm = 0; fm < 4; fm++) {
        size_t r0 = row0 + wm + fm * 16 + (lane >> 2);
        size_t r1 = r0 + 8;
        #pragma unroll
        for (int fn = 0; fn < 4; fn++) {
            int cl = wn + fn * 8 + 2 * (lane & 3);
            size_t cn = col0 + cl;
            float bx = sbias[cl], by = sbias[cl + 1];
            float v0 = acc[fm][fn][0] + bx;
            float v1 = acc[fm][fn][1] + by;
            float v2 = acc[fm][fn][2] + bx;
            float v3 = acc[fm][fn][3] + by;
            if (act == 1) {
                v0 = 0.5f * v0 * (1.f + erff(v0 * 0.70710678118654752f));
                v1 = 0.5f * v1 * (1.f + erff(v1 * 0.70710678118654752f));
                v2 = 0.5f * v2 * (1.f + erff(v2 * 0.70710678118654752f));
                v3 = 0.5f * v3 * (1.f + erff(v3 * 0.70710678118654752f));
            }
            if (R) {
                float2 ra = *(const float2*)(R + r0 * DD + cn);
                float2 rb = *(const float2*)(R + r1 * DD + cn);
                v0 += ra.x; v1 += ra.y; v2 += rb.x; v3 += rb.y;
            }
            *(float2*)(C + r0 * DD + cn) = make_float2(v0, v1);
            *(float2*)(C + r1 * DD + cn) = make_float2(v2, v3);
        }
    }
}

__global__ __launch_bounds__(256, 2) void pgemm_kernel(
    const float* __restrict__ A, const float* __restrict__ W,
    const float* __restrict__ bias, const float* __restrict__ R,
    float* __restrict__ C, int act)
{
    extern __shared__ char smem[];
    gemm_body(A, W, bias, R, C, act,
              (size_t)blockIdx.y * TM, (size_t)blockIdx.x * TN, smem);
}

// Fused Q/K/V projection: grid.x = 18 (3 matrices x 6 col-blocks)
__global__ __launch_bounds__(256, 2) void qkv_gemm_kernel(
    const float* __restrict__ A,
    const float* __restrict__ Wq, const float* __restrict__ Wk,
    const float* __restrict__ Wv,
    const float* __restrict__ bq, const float* __restrict__ bk,
    const float* __restrict__ bv,
    float* __restrict__ Q, float* __restrict__ K, float* __restrict__ V)
{
    extern __shared__ char smem[];
    int mat = blockIdx.x / (DD / TN);
    int cb  = blockIdx.x % (DD / TN);
    const float* W  = (mat == 0) ? Wq : (mat == 1) ? Wk : Wv;
    const float* bi = (mat == 0) ? bq : (mat == 1) ? bk : bv;
    float*       C  = (mat == 0) ? Q  : (mat == 1) ? K  : V;
    gemm_body(A, W, bi, nullptr, C, 0,
              (size_t)blockIdx.y * TM, (size_t)cb * TN, smem);
}

// ---------------------------------------------------------------------------
// Embedding gather
// ---------------------------------------------------------------------------
__global__ __launch_bounds__(256) void embed_kernel(
    const int* __restrict__ idx, const float* __restrict__ emb,
    float* __restrict__ X)
{
    int i   = blockIdx.x * 256 + threadIdx.x;
    int tok = i / (DD / 4);
    int c4  = i % (DD / 4);
    const float4* src = (const float4*)(emb + (size_t)idx[tok] * DD);
    ((float4*)X)[i] = src[c4];
}

// ---------------------------------------------------------------------------
// Rotary cos/sin table
// ---------------------------------------------------------------------------
__global__ __launch_bounds__(256) void rope_table_kernel(
    float* __restrict__ cosT, float* __restrict__ sinT)
{
    int i = blockIdx.x * 256 + threadIdx.x;
    int j = i & 31;
    int l = i >> 5;
    double inv = pow(10000.0, -(double)(2 * j) / (double)HDIM);
    double fr  = (double)l * inv;
    cosT[i] = (float)cos(fr);
    sinT[i] = (float)sin(fr);
}

// ---------------------------------------------------------------------------
// Fused rotary + feature map; grid.y selects Q-path (0) or K-path (1).
// Each thread processes exactly ONE head vector (no register doubling).
// ---------------------------------------------------------------------------
__global__ __launch_bounds__(256) void phi_rot_kernel(
    const float* __restrict__ Q, const float* __restrict__ K,
    const float* __restrict__ omega,
    const float* __restrict__ cosT, const float* __restrict__ sinT,
    const int* __restrict__ mask,
    float* __restrict__ PHQ, float* __restrict__ PHK)
{
    __shared__ float4 som[HDIM * FDIM / 4];
    int tid = threadIdx.x;
    #pragma unroll
    for (int p = 0; p < 2; p++)
        som[tid + p * 256] = ((const float4*)omega)[tid + p * 256];
    __syncthreads();

    int id = blockIdx.x * 256 + tid;
    int n  = id / HH;
    int h  = id % HH;
    int l  = n & (LL - 1);
    int isK = blockIdx.y;

    const float* X = isK ? K : Q;
    float* PH      = isK ? PHK : PHQ;
    float m        = isK ? (float)mask[n] : 1.0f;

    float q[HDIM];
    const float4* src = (const float4*)(X + (size_t)n * DD + h * HDIM);
    #pragma unroll
    for (int i = 0; i < HDIM / 4; i++) {
        float4 v = src[i];
        q[i * 4 + 0] = v.x; q[i * 4 + 1] = v.y;
        q[i * 4 + 2] = v.z; q[i * 4 + 3] = v.w;
    }
    #pragma unroll
    for (int j = 0; j < 32; j++) {
        float c = cosT[l * 32 + j];
        float s = sinT[l * 32 + j];
        float x1 = q[j], x2 = q[j + 32];
        q[j]      = x1 * c - x2 * s;
        q[j + 32] = x2 * c + x1 * s;
    }

    float4* out = (float4*)(PH + (size_t)id * FDIM);
    #pragma unroll
    for (int f4 = 0; f4 < FDIM / 4; f4++) {
        float4 acc = make_float4(0.f, 0.f, 0.f, 0.f);
        #pragma unroll
        for (int d = 0; d < HDIM; d++) {
            float4 w = som[d * 8 + f4];
            acc.x += q[d] * w.x; acc.y += q[d] * w.y;
            acc.z += q[d] * w.z; acc.w += q[d] * w.w;
        }
        acc.x = fmaxf(acc.x, 0.f) * m; acc.y = fmaxf(acc.y, 0.f) * m;
        acc.z = fmaxf(acc.z, 0.f) * m; acc.w = fmaxf(acc.w, 0.f) * m;
        out[f4] = acc;
    }
}

// ---------------------------------------------------------------------------
// KV partial reduction: 4 L-chunks per (b,h), deterministic partial buffers
// ---------------------------------------------------------------------------
__global__ __launch_bounds__(256) void kv_part_kernel(
    const float* __restrict__ PHK, const float* __restrict__ V,
    float* __restrict__ KVP, float* __restrict__ KSP)
{
    __shared__ float sph[32 * FDIM];
    __shared__ float sv [32 * HDIM];
    int bh = blockIdx.x;
    int ch = blockIdx.y;
    int b  = bh / HH;
    int h  = bh % HH;
    int tid = threadIdx.x;
    int f  = tid & 31;
    int dg = tid >> 5;
    float acc[8] = {0.f,0.f,0.f,0.f,0.f,0.f,0.f,0.f};
    float sacc = 0.f;

    int rA  = tid >> 3, cA = (tid & 7) * 4;
    int lbeg = ch * (LL / KVCH), lend = lbeg + LL / KVCH;
    for (int l0 = lbeg; l0 < lend; l0 += 32) {
        *(float4*)&sph[rA * FDIM + cA] =
            *(const float4*)(PHK + ((size_t)(b * LL + l0 + rA) * HH + h) * FDIM + cA);
        #pragma unroll
        for (int p = 0; p < 2; p++) {
            int ii = tid + p * 256;
            int rr = ii >> 4, cc = (ii & 15) * 4;
            *(float4*)&sv[rr * HDIM + cc] =
                *(const float4*)(V + (size_t)(b * LL + l0 + rr) * DD + h * HDIM + cc);
        }
        __syncthreads();
        #pragma unroll 8
        for (int r = 0; r < 32; r++) {
            float ph = sph[r * FDIM + f];
            sacc += ph;
            float4 v0 = *(const float4*)&sv[r * HDIM + dg * 8];
            float4 v1 = *(const float4*)&sv[r * HDIM + dg * 8 + 4];
            acc[0] += ph * v0.x; acc[1] += ph * v0.y;
            acc[2] += ph * v0.z; acc[3] += ph * v0.w;
            acc[4] += ph * v1.x; acc[5] += ph * v1.y;
            acc[6] += ph * v1.z; acc[7] += ph * v1.w;
        }
        __syncthreads();
    }
    float* dst = KVP + (((size_t)ch * NBH + bh) * FDIM + f) * HDIM + dg * 8;
    #pragma unroll
    for (int jj = 0; jj < 8; jj++) dst[jj] = acc[jj];
    if (dg == 0) KSP[((size_t)ch * NBH + bh) * FDIM + f] = sacc;
}

__global__ __launch_bounds__(256) void kv_reduce_kernel(
    const float* __restrict__ KVP, const float* __restrict__ KSP,
    float* __restrict__ KV, float* __restrict__ KSUM)
{
    int i = blockIdx.x * 256 + threadIdx.x;
    const int NKV = NBH * FDIM * HDIM;   // 393216
    if (i < NKV) {
        float s = KVP[i] + KVP[NKV + i] + KVP[2 * NKV + i] + KVP[3 * NKV + i];
        KV[i] = s;
    }
    if (i < NBH * FDIM) {
        const int NS = NBH * FDIM;
        KSUM[i] = KSP[i] + KSP[NS + i] + KSP[2 * NS + i] + KSP[3 * NS + i];
    }
}

// ---------------------------------------------------------------------------
// Attention output
// ---------------------------------------------------------------------------
__global__ __launch_bounds__(256) void attn_out_kernel(
    const float* __restrict__ PHQ, const float* __restrict__ KV,
    const float* __restrict__ KSUM, float* __restrict__ Y)
{
    __shared__ float4 skv[FDIM * HDIM / 4];
    __shared__ float  sks[FDIM];
    int bh  = blockIdx.y;
    int tid = threadIdx.x;
    #pragma unroll
    for (int p = 0; p < 2; p++)
        skv[tid + p * 256] = ((const float4*)(KV + (size_t)bh * FDIM * HDIM))[tid + p * 256];
    if (tid < FDIM) sks[tid] = KSUM[bh * FDIM + tid];
    __syncthreads();

    int b = bh / HH, h = bh % HH;
    size_t n = (size_t)b * LL + blockIdx.x * 256 + tid;

    float ph[FDIM];
    const float4* src = (const float4*)(PHQ + (n * HH + h) * FDIM);
    #pragma unroll
    for (int i = 0; i < FDIM / 4; i++) {
        float4 v = src[i];
        ph[i * 4 + 0] = v.x; ph[i * 4 + 1] = v.y;
        ph[i * 4 + 2] = v.z; ph[i * 4 + 3] = v.w;
    }
    float den = ATTN_EPS;
    #pragma unroll
    for (int fI = 0; fI < FDIM; fI++) den += ph[fI] * sks[fI];
    float z = 1.0f / den;

    float4* outp = (float4*)(Y + n * DD + h * HDIM);
    #pragma unroll
    for (int d4 = 0; d4 < HDIM / 4; d4++) {
        float4 acc = make_float4(0.f, 0.f, 0.f, 0.f);
        #pragma unroll
        for (int fI = 0; fI < FDIM; fI++) {
            float4 kvv = skv[fI * 16 + d4];
            acc.x += ph[fI] * kvv.x; acc.y += ph[fI] * kvv.y;
            acc.z += ph[fI] * kvv.z; acc.w += ph[fI] * kvv.w;
        }
        acc.x *= z; acc.y *= z; acc.z *= z; acc.w *= z;
        outp[d4] = acc;
    }
}

// ---------------------------------------------------------------------------
// Warp-per-row LayerNorm: 8 warps/block, 1 row/warp, shuffle-only reduce
// ---------------------------------------------------------------------------
__global__ __launch_bounds__(256) void ln_kernel(
    const float* __restrict__ in, const float* __restrict__ g,
    const float* __restrict__ b, float* __restrict__ out)
{
    int warp = threadIdx.x >> 5, lane = threadIdx.x & 31;
    size_t row = (size_t)blockIdx.x * 8 + warp;
    const float4* ip = (const float4*)(in + row * DD);

    float4 x[6];
    float s = 0.f, s2 = 0.f;
    #pragma unroll
    for (int i = 0; i < 6; i++) {
        x[i] = ip[lane + i * 32];
        s  += x[i].x + x[i].y + x[i].z + x[i].w;
        s2 += x[i].x * x[i].x + x[i].y * x[i].y
            + x[i].z * x[i].z + x[i].w * x[i].w;
    }
    #pragma unroll
    for (int off = 16; off > 0; off >>= 1) {
        s  += __shfl_xor_sync(0xFFFFFFFF, s,  off);
        s2 += __shfl_xor_sync(0xFFFFFFFF, s2, off);
    }
    float mu   = s * (1.0f / DD);
    float rstd = rsqrtf(s2 * (1.0f / DD) - mu * mu + LN_EPS);

    const float4* gp = (const float4*)g;
    const float4* bp = (const float4*)b;
    float4* op = (float4*)(out + row * DD);
    #pragma unroll
    for (int i = 0; i < 6; i++) {
        float4 gg = gp[lane + i * 32];
        float4 bb = bp[lane + i * 32];
        float4 o;
        o.x = (x[i].x - mu) * rstd * gg.x + bb.x;
        o.y = (x[i].y - mu) * rstd * gg.y + bb.y;
        o.z = (x[i].z - mu) * rstd * gg.z + bb.z;
        o.w = (x[i].w - mu) * rstd * gg.w + bb.w;
        op[lane + i * 32] = o;
    }
}

// ---------------------------------------------------------------------------
// Host orchestration
// ---------------------------------------------------------------------------
extern "C" void kernel_launch(void* const* d_in, const int* in_sizes, int n_in,
                              void* d_out, int out_size)
{
    const int*   idx     = (const int*)  d_in[0];
    const int*   mask    = (const int*)  d_in[1];
    const float* tok_emb = (const float*)d_in[2];
    const float* Wq = (const float*)d_in[3];
    const float* bq = (const float*)d_in[4];
    const float* Wk = (const float*)d_in[5];
    const float* bk = (const float*)d_in[6];
    const float* Wv = (const float*)d_in[7];
    const float* bv = (const float*)d_in[8];
    const float* Wo = (const float*)d_in[9];
    const float* bo = (const float*)d_in[10];
    const float* om = (const float*)d_in[11];
    const float* W1 = (const float*)d_in[12];
    const float* b1 = (const float*)d_in[13];
    const float* W2 = (const float*)d_in[14];
    const float* b2 = (const float*)d_in[15];
    const float* g1 = (const float*)d_in[16];
    const float* be1= (const float*)d_in[17];
    const float* g2 = (const float*)d_in[18];
    const float* be2= (const float*)d_in[19];
    const float* gf = (const float*)d_in[20];
    const float* bf = (const float*)d_in[21];
    float* out = (float*)d_out;

    float *X, *Y, *Q, *K, *V, *PHQ, *PHK, *KV, *KSUM, *KVP, *KSP, *COS, *SIN;
    cudaGetSymbolAddress((void**)&X,    g_X);
    cudaGetSymbolAddress((void**)&Y,    g_Y);
    cudaGetSymbolAddress((void**)&Q,    g_Q);
    cudaGetSymbolAddress((void**)&K,    g_K);
    cudaGetSymbolAddress((void**)&V,    g_V);
    cudaGetSymbolAddress((void**)&PHQ,  g_PHQ);
    cudaGetSymbolAddress((void**)&PHK,  g_PHK);
    cudaGetSymbolAddress((void**)&KV,   g_KV);
    cudaGetSymbolAddress((void**)&KSUM, g_KSUM);
    cudaGetSymbolAddress((void**)&KVP,  g_KVP);
    cudaGetSymbolAddress((void**)&KSP,  g_KSP);
    cudaGetSymbolAddress((void**)&COS,  g_COS);
    cudaGetSymbolAddress((void**)&SIN,  g_SIN);

    cudaFuncSetAttribute(pgemm_kernel,
                         cudaFuncAttributeMaxDynamicSharedMemorySize, SMEM_GEMM);
    cudaFuncSetAttribute(qkv_gemm_kernel,
                         cudaFuncAttributeMaxDynamicSharedMemorySize, SMEM_GEMM);

    const size_t WMAT = (size_t)DD * DD;
    dim3 gGrid(DD / TN, NTOK / TM);      // (6, 256)
    dim3 qkvGrid(3 * DD / TN, NTOK / TM); // (18, 256)

    rope_table_kernel<<<(LL * 32) / 256, 256>>>(COS, SIN);
    embed_kernel<<<(NTOK * DD / 4) / 256, 256>>>(idx, tok_emb, X);

    for (int i = 0; i < NLAYER; i++) {
        const float* om_i = om + (size_t)i * HDIM * FDIM;

        qkv_gemm_kernel<<<qkvGrid, 256, SMEM_GEMM>>>(
            X, Wq + i * WMAT, Wk + i * WMAT, Wv + i * WMAT,
            bq + i * DD, bk + i * DD, bv + i * DD, Q, K, V);

        phi_rot_kernel<<<dim3((NTOK * HH) / 256, 2), 256>>>(
            Q, K, om_i, COS, SIN, mask, PHQ, PHK);

        kv_part_kernel<<<dim3(NBH, KVCH), 256>>>(PHK, V, KVP, KSP);
        kv_reduce_kernel<<<(NBH * FDIM * HDIM) / 256, 256>>>(KVP, KSP, KV, KSUM);

        attn_out_kernel<<<dim3(LL / 256, NBH), 256>>>(PHQ, KV, KSUM, Y);

        // X = Y @ Wo + bo + X
        pgemm_kernel<<<gGrid, 256, SMEM_GEMM>>>(Y, Wo + i * WMAT, bo + i * DD, X, X, 0);
        ln_kernel<<<NTOK / 8, 256>>>(X, g1 + i * DD, be1 + i * DD, X);
        // Q = gelu(X @ W1 + b1)
        pgemm_kernel<<<gGrid, 256, SMEM_GEMM>>>(X, W1 + i * WMAT, b1 + i * DD, nullptr, Q, 1);
        // Y = Q @ W2 + b2 + X
        pgemm_kernel<<<gGrid, 256, SMEM_GEMM>>>(Q, W2 + i * WMAT, b2 + i * DD, X, Y, 0);
        ln_kernel<<<NTOK / 8, 256>>>(Y, g2 + i * DD, be2 + i * DD, X);
    }

    ln_kernel<<<NTOK / 8, 256>>>(X, gf, bf, out);
}

// round 11
// speedup vs baseline: 1.1261x; 1.0431x over previous
#include <cuda_runtime.h>
#include <math.h>
#include <stdint.h>

// Problem constants
#define BB      16
#define LL      2048
#define DD      768
#define HH      12
#define NLAYER  4
#define FDIM    32
#define HDIM    64
#define NTOK    (BB * LL)            // 32768
#define ATTN_EPS 1e-6f
#define LN_EPS   1e-5f
#define NBH     (BB * HH)            // 192
#define KVCH    4                    // kv L-split chunks

// ---------------------------------------------------------------------------
// Scratch buffers
// ---------------------------------------------------------------------------
__device__ float g_X [(size_t)NTOK * DD];
__device__ float g_Y [(size_t)NTOK * DD];
__device__ float g_Q [(size_t)NTOK * DD];
__device__ float g_K [(size_t)NTOK * DD];
__device__ float g_V [(size_t)NTOK * DD];
__device__ float g_PHQ[(size_t)NTOK * HH * FDIM];
__device__ float g_PHK[(size_t)NTOK * HH * FDIM];
__device__ float g_KV  [NBH * FDIM * HDIM];
__device__ float g_KSUM[NBH * FDIM];
__device__ float g_KVP [KVCH * NBH * FDIM * HDIM];
__device__ float g_KSP [KVCH * NBH * FDIM];
__device__ float g_COS [LL * (HDIM / 2)];
__device__ float g_SIN [LL * (HDIM / 2)];

// ---------------------------------------------------------------------------
// PTX helpers
// ---------------------------------------------------------------------------
__device__ __forceinline__ void cpa16(uint32_t d, const void* s) {
    asm volatile("cp.async.cg.shared.global [%0], [%1], 16;" :: "r"(d), "l"(s));
}
#define CPA_COMMIT() asm volatile("cp.async.commit_group;" ::: "memory")
#define CPA_WAIT1()  asm volatile("cp.async.wait_group 1;" ::: "memory")

__device__ __forceinline__ uint32_t smem_u32(const void* p) {
    uint32_t a;
    asm("{ .reg .u64 t; cvta.to.shared.u64 t, %1; cvt.u32.u64 %0, t; }"
        : "=r"(a) : "l"(p));
    return a;
}

__device__ __forceinline__ float tf32_rna(float x) {
    unsigned r;
    asm("cvt.rna.tf32.f32 %0, %1;" : "=r"(r) : "f"(x));
    return __uint_as_float(r);
}

__device__ __forceinline__ void mma_tf32(float* c, const unsigned* a, const unsigned* b) {
    asm volatile(
        "mma.sync.aligned.m16n8k8.row.col.f32.tf32.tf32.f32 "
        "{%0,%1,%2,%3},{%4,%5,%6,%7},{%8,%9},{%0,%1,%2,%3};"
        : "+f"(c[0]), "+f"(c[1]), "+f"(c[2]), "+f"(c[3])
        : "r"(a[0]), "r"(a[1]), "r"(a[2]), "r"(a[3]), "r"(b[0]), "r"(b[1]));
}

// ---------------------------------------------------------------------------
// GEMM body (R4-proven shape): 128x128x32 tile, 8 warps of 64x32,
// cp.async 3-stage. Shared by pgemm_kernel and qkv_gemm_kernel.
// ---------------------------------------------------------------------------
#define TM 128
#define TN 128
#define TBK 32
#define NST 3
#define A_STR 36
#define B_STR 136
#define A_TILE_B (TM * A_STR * 4)           // 18432
#define B_TILE_B (TBK * B_STR * 4)          // 17408
#define STAGE_B  (A_TILE_B + B_TILE_B)      // 35840
#define OFF_BIAS (NST * STAGE_B)            // 107520
#define SMEM_GEMM (OFF_BIAS + TN * 4)       // 108032
#define NKT (DD / TBK)                      // 24

__device__ __forceinline__ void gemm_body(
    const float* __restrict__ A, const float* __restrict__ W,
    const float* __restrict__ bias, const float* __restrict__ R,
    float* __restrict__ C, int act, size_t row0, size_t col0, char* smem)
{
    uint32_t sb = smem_u32(smem);
    int tid = threadIdx.x, lane = tid & 31, warp = tid >> 5;
    int wm = (warp & 1) * 64;
    int wn = (warp >> 1) * 32;

    if (tid < TN) *(float*)(smem + OFF_BIAS + tid * 4) = bias[col0 + tid];

    int ar = tid >> 3, akc = tid & 7;
    int bk = tid >> 5, bnc = tid & 31;
    auto load_stage = [&](int u) {
        uint32_t st = sb + (u % NST) * STAGE_B;
        int k0 = u * TBK;
        #pragma unroll
        for (int i = 0; i < 4; i++) {
            int r = ar + i * 32;
            cpa16(st + r * (A_STR * 4) + akc * 16,
                  A + (row0 + r) * DD + k0 + akc * 4);
        }
        uint32_t bbase = st + A_TILE_B;
        #pragma unroll
        for (int i = 0; i < 4; i++) {
            int k = bk + i * 8;
            cpa16(bbase + k * (B_STR * 4) + bnc * 16,
                  W + (size_t)(k0 + k) * DD + col0 + bnc * 4);
        }
    };

    float acc[4][4][4];
    #pragma unroll
    for (int i = 0; i < 4; i++)
        #pragma unroll
        for (int j = 0; j < 4; j++)
            #pragma unroll
            for (int k = 0; k < 4; k++) acc[i][j][k] = 0.f;

    load_stage(0); CPA_COMMIT();
    load_stage(1); CPA_COMMIT();

    for (int t = 0; t < NKT; t++) {
        CPA_WAIT1();
        __syncthreads();
        if (t + 2 < NKT) load_stage(t + 2);
        CPA_COMMIT();
        const float* sA = (const float*)(smem + (t % NST) * STAGE_B);
        const float* sB = (const float*)(smem + (t % NST) * STAGE_B + A_TILE_B);
        #pragma unroll
        for (int ks = 0; ks < 4; ks++) {
            int kc = ks * 8 + (lane & 3);
            unsigned a[4][4], b[4][2];
            #pragma unroll
            for (int fm = 0; fm < 4; fm++) {
                int r = wm + fm * 16 + (lane >> 2);
                a[fm][0] = __float_as_uint(sA[r * A_STR + kc]);
                a[fm][1] = __float_as_uint(sA[(r + 8) * A_STR + kc]);
                a[fm][2] = __float_as_uint(sA[r * A_STR + kc + 4]);
                a[fm][3] = __float_as_uint(sA[(r + 8) * A_STR + kc + 4]);
            }
            #pragma unroll
            for (int fn = 0; fn < 4; fn++) {
                int cn = wn + fn * 8 + (lane >> 2);
                b[fn][0] = __float_as_uint(sB[kc * B_STR + cn]);
                b[fn][1] = __float_as_uint(sB[(kc + 4) * B_STR + cn]);
            }
            #pragma unroll
            for (int fm = 0; fm < 4; fm++)
                #pragma unroll
                for (int fn = 0; fn < 4; fn++)
                    mma_tf32(acc[fm][fn], a[fm], b[fn]);
        }
    }

    const float* sbias = (const float*)(smem + OFF_BIAS);
    #pragma unroll
    for (int fm = 0; fm < 4; fm++) {
        size_t r0 = row0 + wm + fm * 16 + (lane >> 2);
        size_t r1 = r0 + 8;
        #pragma unroll
        for (int fn = 0; fn < 4; fn++) {
            int cl = wn + fn * 8 + 2 * (lane & 3);
            size_t cn = col0 + cl;
            float bx = sbias[cl], by = sbias[cl + 1];
            float v0 = acc[fm][fn][0] + bx;
            float v1 = acc[fm][fn][1] + by;
            float v2 = acc[fm][fn][2] + bx;
            float v3 = acc[fm][fn][3] + by;
            if (act == 1) {
                v0 = 0.5f * v0 * (1.f + erff(v0 * 0.70710678118654752f));
                v1 = 0.5f * v1 * (1.f + erff(v1 * 0.70710678118654752f));
                v2 = 0.5f * v2 * (1.f + erff(v2 * 0.70710678118654752f));
                v3 = 0.5f * v3 * (1.f + erff(v3 * 0.70710678118654752f));
            }
            if (R) {
                float2 ra = *(const float2*)(R + r0 * DD + cn);
                float2 rb = *(const float2*)(R + r1 * DD + cn);
                v0 += ra.x; v1 += ra.y; v2 += rb.x; v3 += rb.y;
            }
            *(float2*)(C + r0 * DD + cn) = make_float2(v0, v1);
            *(float2*)(C + r1 * DD + cn) = make_float2(v2, v3);
        }
    }
}

__global__ __launch_bounds__(256, 2) void pgemm_kernel(
    const float* __restrict__ A, const float* __restrict__ W,
    const float* __restrict__ bias, const float* __restrict__ R,
    float* __restrict__ C, int act)
{
    extern __shared__ char smem[];
    gemm_body(A, W, bias, R, C, act,
              (size_t)blockIdx.y * TM, (size_t)blockIdx.x * TN, smem);
}

// Fused Q/K/V projection: grid.x = 18 (3 matrices x 6 col-blocks)
__global__ __launch_bounds__(256, 2) void qkv_gemm_kernel(
    const float* __restrict__ A,
    const float* __restrict__ Wq, const float* __restrict__ Wk,
    const float* __restrict__ Wv,
    const float* __restrict__ bq, const float* __restrict__ bk,
    const float* __restrict__ bv,
    float* __restrict__ Q, float* __restrict__ K, float* __restrict__ V)
{
    extern __shared__ char smem[];
    int mat = blockIdx.x / (DD / TN);
    int cb  = blockIdx.x % (DD / TN);
    const float* W  = (mat == 0) ? Wq : (mat == 1) ? Wk : Wv;
    const float* bi = (mat == 0) ? bq : (mat == 1) ? bk : bv;
    float*       C  = (mat == 0) ? Q  : (mat == 1) ? K  : V;
    gemm_body(A, W, bi, nullptr, C, 0,
              (size_t)blockIdx.y * TM, (size_t)cb * TN, smem);
}

// ---------------------------------------------------------------------------
// Embedding gather
// ---------------------------------------------------------------------------
__global__ __launch_bounds__(256) void embed_kernel(
    const int* __restrict__ idx, const float* __restrict__ emb,
    float* __restrict__ X)
{
    int i   = blockIdx.x * 256 + threadIdx.x;
    int tok = i / (DD / 4);
    int c4  = i % (DD / 4);
    const float4* src = (const float4*)(emb + (size_t)idx[tok] * DD);
    ((float4*)X)[i] = src[c4];
}

// ---------------------------------------------------------------------------
// Rotary cos/sin table
// ---------------------------------------------------------------------------
__global__ __launch_bounds__(256) void rope_table_kernel(
    float* __restrict__ cosT, float* __restrict__ sinT)
{
    int i = blockIdx.x * 256 + threadIdx.x;
    int j = i & 31;
    int l = i >> 5;
    double inv = pow(10000.0, -(double)(2 * j) / (double)HDIM);
    double fr  = (double)l * inv;
    cosT[i] = (float)cos(fr);
    sinT[i] = (float)sin(fr);
}

// ---------------------------------------------------------------------------
// Tensor-core phi: PH = relu( rot(X) @ omega ) * mask?
// 128 rows/block. A split hi/lo (2 tf32 MMAs) so phi error = omega tf32 only.
// A smem [128][68] (bank (4r+kc)%32 bijective); B smem [64][40] ((8k+n)%32).
// grid = (3072, 2): y=0 -> Q path, y=1 -> K path (masked).
// ---------------------------------------------------------------------------
#define PHI_A_STR 68
#define PHI_B_STR 40
#define PHI_AB (128 * PHI_A_STR)                 // floats per A buffer
#define SMEM_PHI ((2 * PHI_AB + HDIM * PHI_B_STR) * 4)   // 79872 bytes

__global__ __launch_bounds__(256, 2) void phi_mma_kernel(
    const float* __restrict__ Q, const float* __restrict__ K,
    const float* __restrict__ omega,
    const float* __restrict__ cosT, const float* __restrict__ sinT,
    const int* __restrict__ mask,
    float* __restrict__ PHQ, float* __restrict__ PHK)
{
    extern __shared__ float sm[];
    float* Ahi = sm;
    float* Alo = sm + PHI_AB;
    float* Bs  = sm + 2 * PHI_AB;

    int tid = threadIdx.x, lane = tid & 31, warp = tid >> 5;
    int isK = blockIdx.y;
    const float* X = isK ? K : Q;
    float* PH      = isK ? PHK : PHQ;

    // omega -> smem [d][40], RNA-converted to tf32
    {
        int i0 = tid * 8;
        #pragma unroll
        for (int u = 0; u < 2; u++) {
            int i = i0 + u * 4;
            float4 v = *(const float4*)(omega + i);
            int d = i >> 5, f = i & 31;
            Bs[d * PHI_B_STR + f + 0] = tf32_rna(v.x);
            Bs[d * PHI_B_STR + f + 1] = tf32_rna(v.y);
            Bs[d * PHI_B_STR + f + 2] = tf32_rna(v.z);
            Bs[d * PHI_B_STR + f + 3] = tf32_rna(v.w);
        }
    }

    // load + rotate + hi/lo split: 2 threads per row, 16 dims each (+ pairs)
    {
        int row = tid >> 1;
        int j0  = (tid & 1) * 16;
        int id  = blockIdx.x * 128 + row;
        int n   = id / HH;
        int l   = n & (LL - 1);
        const float* xp = X + (size_t)n * DD + (id % HH) * HDIM;
        #pragma unroll
        for (int jj = 0; jj < 4; jj++) {
            int j = j0 + jj * 4;
            float4 x1 = *(const float4*)(xp + j);
            float4 x2 = *(const float4*)(xp + j + 32);
            float4 c  = *(const float4*)(cosT + l * 32 + j);
            float4 s  = *(const float4*)(sinT + l * 32 + j);
            float r1[4], r2[4];
            r1[0] = x1.x * c.x - x2.x * s.x;  r2[0] = x2.x * c.x + x1.x * s.x;
            r1[1] = x1.y * c.y - x2.y * s.y;  r2[1] = x2.y * c.y + x1.y * s.y;
            r1[2] = x1.z * c.z - x2.z * s.z;  r2[2] = x2.z * c.z + x1.z * s.z;
            r1[3] = x1.w * c.w - x2.w * s.w;  r2[3] = x2.w * c.w + x1.w * s.w;
            float* ahi1 = Ahi + row * PHI_A_STR + j;
            float* alo1 = Alo + row * PHI_A_STR + j;
            #pragma unroll
            for (int e = 0; e < 4; e++) {
                float h1 = tf32_rna(r1[e]);
                float h2 = tf32_rna(r2[e]);
                ahi1[e]      = h1;
                ahi1[e + 32] = h2;
                alo1[e]      = tf32_rna(r1[e] - h1);
                alo1[e + 32] = tf32_rna(r2[e] - h2);
            }
        }
    }
    __syncthreads();

    // MMA: warp handles 16 rows x 32 cols, K=64 (8 ksteps), hi+lo
    float acc[4][4];
    #pragma unroll
    for (int i = 0; i < 4; i++)
        #pragma unroll
        for (int j = 0; j < 4; j++) acc[i][j] = 0.f;

    int rbase = warp * 16 + (lane >> 2);
    #pragma unroll
    for (int ks = 0; ks < 8; ks++) {
        int kc = ks * 8 + (lane & 3);
        unsigned ahi[4], alo[4];
        ahi[0] = __float_as_uint(Ahi[rbase * PHI_A_STR + kc]);
        ahi[1] = __float_as_uint(Ahi[(rbase + 8) * PHI_A_STR + kc]);
        ahi[2] = __float_as_uint(Ahi[rbase * PHI_A_STR + kc + 4]);
        ahi[3] = __float_as_uint(Ahi[(rbase + 8) * PHI_A_STR + kc + 4]);
        alo[0] = __float_as_uint(Alo[rbase * PHI_A_STR + kc]);
        alo[1] = __float_as_uint(Alo[(rbase + 8) * PHI_A_STR + kc]);
        alo[2] = __float_as_uint(Alo[rbase * PHI_A_STR + kc + 4]);
        alo[3] = __float_as_uint(Alo[(rbase + 8) * PHI_A_STR + kc + 4]);
        #pragma unroll
        for (int fn = 0; fn < 4; fn++) {
            int cn = fn * 8 + (lane >> 2);
            unsigned b[2];
            b[0] = __float_as_uint(Bs[kc * PHI_B_STR + cn]);
            b[1] = __float_as_uint(Bs[(kc + 4) * PHI_B_STR + cn]);
            mma_tf32(acc[fn], alo, b);
            mma_tf32(acc[fn], ahi, b);
        }
    }

    // epilogue: relu, mask, store
    size_t id0 = (size_t)blockIdx.x * 128 + warp * 16 + (lane >> 2);
    size_t id1 = id0 + 8;
    float m0 = isK ? (float)mask[id0 / HH] : 1.0f;
    float m1 = isK ? (float)mask[id1 / HH] : 1.0f;
    #pragma unroll
    for (int fn = 0; fn < 4; fn++) {
        int cl = fn * 8 + 2 * (lane & 3);
        float v0 = fmaxf(acc[fn][0], 0.f) * m0;
        float v1 = fmaxf(acc[fn][1], 0.f) * m0;
        float v2 = fmaxf(acc[fn][2], 0.f) * m1;
        float v3 = fmaxf(acc[fn][3], 0.f) * m1;
        *(float2*)(PH + id0 * FDIM + cl) = make_float2(v0, v1);
        *(float2*)(PH + id1 * FDIM + cl) = make_float2(v2, v3);
    }
}

// ---------------------------------------------------------------------------
// KV partial reduction: 4 L-chunks per (b,h), deterministic partial buffers
// ---------------------------------------------------------------------------
__global__ __launch_bounds__(256) void kv_part_kernel(
    const float* __restrict__ PHK, const float* __restrict__ V,
    float* __restrict__ KVP, float* __restrict__ KSP)
{
    __shared__ float sph[32 * FDIM];
    __shared__ float sv [32 * HDIM];
    int bh = blockIdx.x;
    int ch = blockIdx.y;
    int b  = bh / HH;
    int h  = bh % HH;
    int tid = threadIdx.x;
    int f  = tid & 31;
    int dg = tid >> 5;
    float acc[8] = {0.f,0.f,0.f,0.f,0.f,0.f,0.f,0.f};
    float sacc = 0.f;

    int rA  = tid >> 3, cA = (tid & 7) * 4;
    int lbeg = ch * (LL / KVCH), lend = lbeg + LL / KVCH;
    for (int l0 = lbeg; l0 < lend; l0 += 32) {
        *(float4*)&sph[rA * FDIM + cA] =
            *(const float4*)(PHK + ((size_t)(b * LL + l0 + rA) * HH + h) * FDIM + cA);
        #pragma unroll
        for (int p = 0; p < 2; p++) {
            int ii = tid + p * 256;
            int rr = ii >> 4, cc = (ii & 15) * 4;
            *(float4*)&sv[rr * HDIM + cc] =
                *(const float4*)(V + (size_t)(b * LL + l0 + rr) * DD + h * HDIM + cc);
        }
        __syncthreads();
        #pragma unroll 8
        for (int r = 0; r < 32; r++) {
            float ph = sph[r * FDIM + f];
            sacc += ph;
            float4 v0 = *(const float4*)&sv[r * HDIM + dg * 8];
            float4 v1 = *(const float4*)&sv[r * HDIM + dg * 8 + 4];
            acc[0] += ph * v0.x; acc[1] += ph * v0.y;
            acc[2] += ph * v0.z; acc[3] += ph * v0.w;
            acc[4] += ph * v1.x; acc[5] += ph * v1.y;
            acc[6] += ph * v1.z; acc[7] += ph * v1.w;
        }
        __syncthreads();
    }
    float* dst = KVP + (((size_t)ch * NBH + bh) * FDIM + f) * HDIM + dg * 8;
    #pragma unroll
    for (int jj = 0; jj < 8; jj++) dst[jj] = acc[jj];
    if (dg == 0) KSP[((size_t)ch * NBH + bh) * FDIM + f] = sacc;
}

__global__ __launch_bounds__(256) void kv_reduce_kernel(
    const float* __restrict__ KVP, const float* __restrict__ KSP,
    float* __restrict__ KV, float* __restrict__ KSUM)
{
    int i = blockIdx.x * 256 + threadIdx.x;
    const int NKV = NBH * FDIM * HDIM;   // 393216
    if (i < NKV) {
        float s = KVP[i] + KVP[NKV + i] + KVP[2 * NKV + i] + KVP[3 * NKV + i];
        KV[i] = s;
    }
    if (i < NBH * FDIM) {
        const int NS = NBH * FDIM;
        KSUM[i] = KSP[i] + KSP[NS + i] + KSP[2 * NS + i] + KSP[3 * NS + i];
    }
}

// ---------------------------------------------------------------------------
// Attention output
// ---------------------------------------------------------------------------
__global__ __launch_bounds__(256) void attn_out_kernel(
    const float* __restrict__ PHQ, const float* __restrict__ KV,
    const float* __restrict__ KSUM, float* __restrict__ Y)
{
    __shared__ float4 skv[FDIM * HDIM / 4];
    __shared__ float  sks[FDIM];
    int bh  = blockIdx.y;
    int tid = threadIdx.x;
    #pragma unroll
    for (int p = 0; p < 2; p++)
        skv[tid + p * 256] = ((const float4*)(KV + (size_t)bh * FDIM * HDIM))[tid + p * 256];
    if (tid < FDIM) sks[tid] = KSUM[bh * FDIM + tid];
    __syncthreads();

    int b = bh / HH, h = bh % HH;
    size_t n = (size_t)b * LL + blockIdx.x * 256 + tid;

    float ph[FDIM];
    const float4* src = (const float4*)(PHQ + (n * HH + h) * FDIM);
    #pragma unroll
    for (int i = 0; i < FDIM / 4; i++) {
        float4 v = src[i];
        ph[i * 4 + 0] = v.x; ph[i * 4 + 1] = v.y;
        ph[i * 4 + 2] = v.z; ph[i * 4 + 3] = v.w;
    }
    float den = ATTN_EPS;
    #pragma unroll
    for (int fI = 0; fI < FDIM; fI++) den += ph[fI] * sks[fI];
    float z = 1.0f / den;

    float4* outp = (float4*)(Y + n * DD + h * HDIM);
    #pragma unroll
    for (int d4 = 0; d4 < HDIM / 4; d4++) {
        float4 acc = make_float4(0.f, 0.f, 0.f, 0.f);
        #pragma unroll
        for (int fI = 0; fI < FDIM; fI++) {
            float4 kvv = skv[fI * 16 + d4];
            acc.x += ph[fI] * kvv.x; acc.y += ph[fI] * kvv.y;
            acc.z += ph[fI] * kvv.z; acc.w += ph[fI] * kvv.w;
        }
        acc.x *= z; acc.y *= z; acc.z *= z; acc.w *= z;
        outp[d4] = acc;
    }
}

// ---------------------------------------------------------------------------
// Warp-per-row LayerNorm: 8 warps/block, 1 row/warp, shuffle-only reduce
// ---------------------------------------------------------------------------
__global__ __launch_bounds__(256) void ln_kernel(
    const float* __restrict__ in, const float* __restrict__ g,
    const float* __restrict__ b, float* __restrict__ out)
{
    int warp = threadIdx.x >> 5, lane = threadIdx.x & 31;
    size_t row = (size_t)blockIdx.x * 8 + warp;
    const float4* ip = (const float4*)(in + row * DD);

    float4 x[6];
    float s = 0.f, s2 = 0.f;
    #pragma unroll
    for (int i = 0; i < 6; i++) {
        x[i] = ip[lane + i * 32];
        s  += x[i].x + x[i].y + x[i].z + x[i].w;
        s2 += x[i].x * x[i].x + x[i].y * x[i].y
            + x[i].z * x[i].z + x[i].w * x[i].w;
    }
    #pragma unroll
    for (int off = 16; off > 0; off >>= 1) {
        s  += __shfl_xor_sync(0xFFFFFFFF, s,  off);
        s2 += __shfl_xor_sync(0xFFFFFFFF, s2, off);
    }
    float mu   = s * (1.0f / DD);
    float rstd = rsqrtf(s2 * (1.0f / DD) - mu * mu + LN_EPS);

    const float4* gp = (const float4*)g;
    const float4* bp = (const float4*)b;
    float4* op = (float4*)(out + row * DD);
    #pragma unroll
    for (int i = 0; i < 6; i++) {
        float4 gg = gp[lane + i * 32];
        float4 bb = bp[lane + i * 32];
        float4 o;
        o.x = (x[i].x - mu) * rstd * gg.x + bb.x;
        o.y = (x[i].y - mu) * rstd * gg.y + bb.y;
        o.z = (x[i].z - mu) * rstd * gg.z + bb.z;
        o.w = (x[i].w - mu) * rstd * gg.w + bb.w;
        op[lane + i * 32] = o;
    }
}

// ---------------------------------------------------------------------------
// Host orchestration
// ---------------------------------------------------------------------------
extern "C" void kernel_launch(void* const* d_in, const int* in_sizes, int n_in,
                              void* d_out, int out_size)
{
    const int*   idx     = (const int*)  d_in[0];
    const int*   mask    = (const int*)  d_in[1];
    const float* tok_emb = (const float*)d_in[2];
    const float* Wq = (const float*)d_in[3];
    const float* bq = (const float*)d_in[4];
    const float* Wk = (const float*)d_in[5];
    const float* bk = (const float*)d_in[6];
    const float* Wv = (const float*)d_in[7];
    const float* bv = (const float*)d_in[8];
    const float* Wo = (const float*)d_in[9];
    const float* bo = (const float*)d_in[10];
    const float* om = (const float*)d_in[11];
    const float* W1 = (const float*)d_in[12];
    const float* b1 = (const float*)d_in[13];
    const float* W2 = (const float*)d_in[14];
    const float* b2 = (const float*)d_in[15];
    const float* g1 = (const float*)d_in[16];
    const float* be1= (const float*)d_in[17];
    const float* g2 = (const float*)d_in[18];
    const float* be2= (const float*)d_in[19];
    const float* gf = (const float*)d_in[20];
    const float* bf = (const float*)d_in[21];
    float* out = (float*)d_out;

    float *X, *Y, *Q, *K, *V, *PHQ, *PHK, *KV, *KSUM, *KVP, *KSP, *COS, *SIN;
    cudaGetSymbolAddress((void**)&X,    g_X);
    cudaGetSymbolAddress((void**)&Y,    g_Y);
    cudaGetSymbolAddress((void**)&Q,    g_Q);
    cudaGetSymbolAddress((void**)&K,    g_K);
    cudaGetSymbolAddress((void**)&V,    g_V);
    cudaGetSymbolAddress((void**)&PHQ,  g_PHQ);
    cudaGetSymbolAddress((void**)&PHK,  g_PHK);
    cudaGetSymbolAddress((void**)&KV,   g_KV);
    cudaGetSymbolAddress((void**)&KSUM, g_KSUM);
    cudaGetSymbolAddress((void**)&KVP,  g_KVP);
    cudaGetSymbolAddress((void**)&KSP,  g_KSP);
    cudaGetSymbolAddress((void**)&COS,  g_COS);
    cudaGetSymbolAddress((void**)&SIN,  g_SIN);

    cudaFuncSetAttribute(pgemm_kernel,
                         cudaFuncAttributeMaxDynamicSharedMemorySize, SMEM_GEMM);
    cudaFuncSetAttribute(qkv_gemm_kernel,
                         cudaFuncAttributeMaxDynamicSharedMemorySize, SMEM_GEMM);
    cudaFuncSetAttribute(phi_mma_kernel,
                         cudaFuncAttributeMaxDynamicSharedMemorySize, SMEM_PHI);

    const size_t WMAT = (size_t)DD * DD;
    dim3 gGrid(DD / TN, NTOK / TM);       // (6, 256)
    dim3 qkvGrid(3 * DD / TN, NTOK / TM); // (18, 256)
    dim3 phiGrid((NTOK * HH) / 128, 2);   // (3072, 2)

    rope_table_kernel<<<(LL * 32) / 256, 256>>>(COS, SIN);
    embed_kernel<<<(NTOK * DD / 4) / 256, 256>>>(idx, tok_emb, X);

    for (int i = 0; i < NLAYER; i++) {
        const float* om_i = om + (size_t)i * HDIM * FDIM;

        qkv_gemm_kernel<<<qkvGrid, 256, SMEM_GEMM>>>(
            X, Wq + i * WMAT, Wk + i * WMAT, Wv + i * WMAT,
            bq + i * DD, bk + i * DD, bv + i * DD, Q, K, V);

        phi_mma_kernel<<<phiGrid, 256, SMEM_PHI>>>(
            Q, K, om_i, COS, SIN, mask, PHQ, PHK);

        kv_part_kernel<<<dim3(NBH, KVCH), 256>>>(PHK, V, KVP, KSP);
        kv_reduce_kernel<<<(NBH * FDIM * HDIM) / 256, 256>>>(KVP, KSP, KV, KSUM);

        attn_out_kernel<<<dim3(LL / 256, NBH), 256>>>(PHQ, KV, KSUM, Y);

        // X = Y @ Wo + bo + X
        pgemm_kernel<<<gGrid, 256, SMEM_GEMM>>>(Y, Wo + i * WMAT, bo + i * DD, X, X, 0);
        ln_kernel<<<NTOK / 8, 256>>>(X, g1 + i * DD, be1 + i * DD, X);
        // Q = gelu(X @ W1 + b1)
        pgemm_kernel<<<gGrid, 256, SMEM_GEMM>>>(X, W1 + i * WMAT, b1 + i * DD, nullptr, Q, 1);
        // Y = Q @ W2 + b2 + X
        pgemm_kernel<<<gGrid, 256, SMEM_GEMM>>>(Q, W2 + i * WMAT, b2 + i * DD, X, Y, 0);
        ln_kernel<<<NTOK / 8, 256>>>(Y, g2 + i * DD, be2 + i * DD, X);
    }

    ln_kernel<<<NTOK / 8, 256>>>(X, gf, bf, out);
}

// round 12
// speedup vs baseline: 1.1676x; 1.0368x over previous
#include <cuda_runtime.h>
#include <math.h>
#include <stdint.h>

// Problem constants
#define BB      16
#define LL      2048
#define DD      768
#define HH      12
#define NLAYER  4
#define FDIM    32
#define HDIM    64
#define NTOK    (BB * LL)            // 32768
#define ATTN_EPS 1e-6f
#define LN_EPS   1e-5f
#define NBH     (BB * HH)            // 192
#define KVCH    4                    // kv L-split chunks

// ---------------------------------------------------------------------------
// Scratch buffers
// ---------------------------------------------------------------------------
__device__ float g_X [(size_t)NTOK * DD];
__device__ float g_Y [(size_t)NTOK * DD];
__device__ float g_Q [(size_t)NTOK * DD];
__device__ float g_K [(size_t)NTOK * DD];
__device__ float g_V [(size_t)NTOK * DD];
__device__ float g_PHK[(size_t)NTOK * HH * FDIM];
__device__ float g_KV  [NBH * FDIM * HDIM];
__device__ float g_KSUM[NBH * FDIM];
__device__ float g_KVP [KVCH * NBH * FDIM * HDIM];
__device__ float g_KSP [KVCH * NBH * FDIM];
__device__ float g_COS [LL * (HDIM / 2)];
__device__ float g_SIN [LL * (HDIM / 2)];

// ---------------------------------------------------------------------------
// PTX helpers
// ---------------------------------------------------------------------------
__device__ __forceinline__ void cpa16(uint32_t d, const void* s) {
    asm volatile("cp.async.cg.shared.global [%0], [%1], 16;" :: "r"(d), "l"(s));
}
#define CPA_COMMIT() asm volatile("cp.async.commit_group;" ::: "memory")
#define CPA_WAIT1()  asm volatile("cp.async.wait_group 1;" ::: "memory")

__device__ __forceinline__ uint32_t smem_u32(const void* p) {
    uint32_t a;
    asm("{ .reg .u64 t; cvta.to.shared.u64 t, %1; cvt.u32.u64 %0, t; }"
        : "=r"(a) : "l"(p));
    return a;
}

__device__ __forceinline__ float tf32_rna(float x) {
    unsigned r;
    asm("cvt.rna.tf32.f32 %0, %1;" : "=r"(r) : "f"(x));
    return __uint_as_float(r);
}

__device__ __forceinline__ void mma_tf32(float* c, const unsigned* a, const unsigned* b) {
    asm volatile(
        "mma.sync.aligned.m16n8k8.row.col.f32.tf32.tf32.f32 "
        "{%0,%1,%2,%3},{%4,%5,%6,%7},{%8,%9},{%0,%1,%2,%3};"
        : "+f"(c[0]), "+f"(c[1]), "+f"(c[2]), "+f"(c[3])
        : "r"(a[0]), "r"(a[1]), "r"(a[2]), "r"(a[3]), "r"(b[0]), "r"(b[1]));
}

// ---------------------------------------------------------------------------
// GEMM body (R4-proven shape): 128x128x32 tile, 8 warps of 64x32,
// cp.async 3-stage. Shared by pgemm_kernel and qkv_gemm_kernel.
// ---------------------------------------------------------------------------
#define TM 128
#define TN 128
#define TBK 32
#define NST 3
#define A_STR 36
#define B_STR 136
#define A_TILE_B (TM * A_STR * 4)           // 18432
#define B_TILE_B (TBK * B_STR * 4)          // 17408
#define STAGE_B  (A_TILE_B + B_TILE_B)      // 35840
#define OFF_BIAS (NST * STAGE_B)            // 107520
#define SMEM_GEMM (OFF_BIAS + TN * 4)       // 108032
#define NKT (DD / TBK)                      // 24

__device__ __forceinline__ void gemm_body(
    const float* __restrict__ A, const float* __restrict__ W,
    const float* __restrict__ bias, const float* __restrict__ R,
    float* __restrict__ C, int act, size_t row0, size_t col0, char* smem)
{
    uint32_t sb = smem_u32(smem);
    int tid = threadIdx.x, lane = tid & 31, warp = tid >> 5;
    int wm = (warp & 1) * 64;
    int wn = (warp >> 1) * 32;

    if (tid < TN) *(float*)(smem + OFF_BIAS + tid * 4) = bias[col0 + tid];

    int ar = tid >> 3, akc = tid & 7;
    int bk = tid >> 5, bnc = tid & 31;
    auto load_stage = [&](int u) {
        uint32_t st = sb + (u % NST) * STAGE_B;
        int k0 = u * TBK;
        #pragma unroll
        for (int i = 0; i < 4; i++) {
            int r = ar + i * 32;
            cpa16(st + r * (A_STR * 4) + akc * 16,
                  A + (row0 + r) * DD + k0 + akc * 4);
        }
        uint32_t bbase = st + A_TILE_B;
        #pragma unroll
        for (int i = 0; i < 4; i++) {
            int k = bk + i * 8;
            cpa16(bbase + k * (B_STR * 4) + bnc * 16,
                  W + (size_t)(k0 + k) * DD + col0 + bnc * 4);
        }
    };

    float acc[4][4][4];
    #pragma unroll
    for (int i = 0; i < 4; i++)
        #pragma unroll
        for (int j = 0; j < 4; j++)
            #pragma unroll
            for (int k = 0; k < 4; k++) acc[i][j][k] = 0.f;

    load_stage(0); CPA_COMMIT();
    load_stage(1); CPA_COMMIT();

    for (int t = 0; t < NKT; t++) {
        CPA_WAIT1();
        __syncthreads();
        if (t + 2 < NKT) load_stage(t + 2);
        CPA_COMMIT();
        const float* sA = (const float*)(smem + (t % NST) * STAGE_B);
        const float* sB = (const float*)(smem + (t % NST) * STAGE_B + A_TILE_B);
        #pragma unroll
        for (int ks = 0; ks < 4; ks++) {
            int kc = ks * 8 + (lane & 3);
            unsigned a[4][4], b[4][2];
            #pragma unroll
            for (int fm = 0; fm < 4; fm++) {
                int r = wm + fm * 16 + (lane >> 2);
                a[fm][0] = __float_as_uint(sA[r * A_STR + kc]);
                a[fm][1] = __float_as_uint(sA[(r + 8) * A_STR + kc]);
                a[fm][2] = __float_as_uint(sA[r * A_STR + kc + 4]);
                a[fm][3] = __float_as_uint(sA[(r + 8) * A_STR + kc + 4]);
            }
            #pragma unroll
            for (int fn = 0; fn < 4; fn++) {
                int cn = wn + fn * 8 + (lane >> 2);
                b[fn][0] = __float_as_uint(sB[kc * B_STR + cn]);
                b[fn][1] = __float_as_uint(sB[(kc + 4) * B_STR + cn]);
            }
            #pragma unroll
            for (int fm = 0; fm < 4; fm++)
                #pragma unroll
                for (int fn = 0; fn < 4; fn++)
                    mma_tf32(acc[fm][fn], a[fm], b[fn]);
        }
    }

    const float* sbias = (const float*)(smem + OFF_BIAS);
    #pragma unroll
    for (int fm = 0; fm < 4; fm++) {
        size_t r0 = row0 + wm + fm * 16 + (lane >> 2);
        size_t r1 = r0 + 8;
        #pragma unroll
        for (int fn = 0; fn < 4; fn++) {
            int cl = wn + fn * 8 + 2 * (lane & 3);
            size_t cn = col0 + cl;
            float bx = sbias[cl], by = sbias[cl + 1];
            float v0 = acc[fm][fn][0] + bx;
            float v1 = acc[fm][fn][1] + by;
            float v2 = acc[fm][fn][2] + bx;
            float v3 = acc[fm][fn][3] + by;
            if (act == 1) {
                v0 = 0.5f * v0 * (1.f + erff(v0 * 0.70710678118654752f));
                v1 = 0.5f * v1 * (1.f + erff(v1 * 0.70710678118654752f));
                v2 = 0.5f * v2 * (1.f + erff(v2 * 0.70710678118654752f));
                v3 = 0.5f * v3 * (1.f + erff(v3 * 0.70710678118654752f));
            }
            if (R) {
                float2 ra = *(const float2*)(R + r0 * DD + cn);
                float2 rb = *(const float2*)(R + r1 * DD + cn);
                v0 += ra.x; v1 += ra.y; v2 += rb.x; v3 += rb.y;
            }
            *(float2*)(C + r0 * DD + cn) = make_float2(v0, v1);
            *(float2*)(C + r1 * DD + cn) = make_float2(v2, v3);
        }
    }
}

__global__ __launch_bounds__(256, 2) void pgemm_kernel(
    const float* __restrict__ A, const float* __restrict__ W,
    const float* __restrict__ bias, const float* __restrict__ R,
    float* __restrict__ C, int act)
{
    extern __shared__ char smem[];
    gemm_body(A, W, bias, R, C, act,
              (size_t)blockIdx.y * TM, (size_t)blockIdx.x * TN, smem);
}

// Fused Q/K/V projection: grid.x = 18 (3 matrices x 6 col-blocks)
__global__ __launch_bounds__(256, 2) void qkv_gemm_kernel(
    const float* __restrict__ A,
    const float* __restrict__ Wq, const float* __restrict__ Wk,
    const float* __restrict__ Wv,
    const float* __restrict__ bq, const float* __restrict__ bk,
    const float* __restrict__ bv,
    float* __restrict__ Q, float* __restrict__ K, float* __restrict__ V)
{
    extern __shared__ char smem[];
    int mat = blockIdx.x / (DD / TN);
    int cb  = blockIdx.x % (DD / TN);
    const float* W  = (mat == 0) ? Wq : (mat == 1) ? Wk : Wv;
    const float* bi = (mat == 0) ? bq : (mat == 1) ? bk : bv;
    float*       C  = (mat == 0) ? Q  : (mat == 1) ? K  : V;
    gemm_body(A, W, bi, nullptr, C, 0,
              (size_t)blockIdx.y * TM, (size_t)cb * TN, smem);
}

// ---------------------------------------------------------------------------
// Embedding gather
// ---------------------------------------------------------------------------
__global__ __launch_bounds__(256) void embed_kernel(
    const int* __restrict__ idx, const float* __restrict__ emb,
    float* __restrict__ X)
{
    int i   = blockIdx.x * 256 + threadIdx.x;
    int tok = i / (DD / 4);
    int c4  = i % (DD / 4);
    const float4* src = (const float4*)(emb + (size_t)idx[tok] * DD);
    ((float4*)X)[i] = src[c4];
}

// ---------------------------------------------------------------------------
// Rotary cos/sin table
// ---------------------------------------------------------------------------
__global__ __launch_bounds__(256) void rope_table_kernel(
    float* __restrict__ cosT, float* __restrict__ sinT)
{
    int i = blockIdx.x * 256 + threadIdx.x;
    int j = i & 31;
    int l = i >> 5;
    double inv = pow(10000.0, -(double)(2 * j) / (double)HDIM);
    double fr  = (double)l * inv;
    cosT[i] = (float)cos(fr);
    sinT[i] = (float)sin(fr);
}

// ---------------------------------------------------------------------------
// Tensor-core phi for K only: PHK = relu( rot(K) @ omega ) * mask
// 128 rows/block, single tf32 MMA (no hi/lo split).
// ---------------------------------------------------------------------------
#define PHI_A_STR 68
#define PHI_B_STR 40
#define SMEM_PHI ((128 * PHI_A_STR + HDIM * PHI_B_STR) * 4)   // 45056 bytes

__global__ __launch_bounds__(256, 2) void phik_mma_kernel(
    const float* __restrict__ K, const float* __restrict__ omega,
    const float* __restrict__ cosT, const float* __restrict__ sinT,
    const int* __restrict__ mask, float* __restrict__ PHK)
{
    extern __shared__ float sm[];
    float* As = sm;
    float* Bs = sm + 128 * PHI_A_STR;

    int tid = threadIdx.x, lane = tid & 31, warp = tid >> 5;

    // omega -> smem [d][40], RNA tf32
    {
        int i0 = tid * 8;
        #pragma unroll
        for (int u = 0; u < 2; u++) {
            int i = i0 + u * 4;
            float4 v = *(const float4*)(omega + i);
            int d = i >> 5, f = i & 31;
            Bs[d * PHI_B_STR + f + 0] = tf32_rna(v.x);
            Bs[d * PHI_B_STR + f + 1] = tf32_rna(v.y);
            Bs[d * PHI_B_STR + f + 2] = tf32_rna(v.z);
            Bs[d * PHI_B_STR + f + 3] = tf32_rna(v.w);
        }
    }

    // load + rotate: 2 threads per row, 16 dims each
    {
        int row = tid >> 1;
        int j0  = (tid & 1) * 16;
        int id  = blockIdx.x * 128 + row;
        int n   = id / HH;
        int l   = n & (LL - 1);
        const float* xp = K + (size_t)n * DD + (id % HH) * HDIM;
        #pragma unroll
        for (int jj = 0; jj < 4; jj++) {
            int j = j0 + jj * 4;
            float4 x1 = *(const float4*)(xp + j);
            float4 x2 = *(const float4*)(xp + j + 32);
            float4 c  = *(const float4*)(cosT + l * 32 + j);
            float4 s  = *(const float4*)(sinT + l * 32 + j);
            float* a1 = As + row * PHI_A_STR + j;
            a1[0]  = tf32_rna(x1.x * c.x - x2.x * s.x);
            a1[32] = tf32_rna(x2.x * c.x + x1.x * s.x);
            a1[1]  = tf32_rna(x1.y * c.y - x2.y * s.y);
            a1[33] = tf32_rna(x2.y * c.y + x1.y * s.y);
            a1[2]  = tf32_rna(x1.z * c.z - x2.z * s.z);
            a1[34] = tf32_rna(x2.z * c.z + x1.z * s.z);
            a1[3]  = tf32_rna(x1.w * c.w - x2.w * s.w);
            a1[35] = tf32_rna(x2.w * c.w + x1.w * s.w);
        }
    }
    __syncthreads();

    float acc[4][4];
    #pragma unroll
    for (int i = 0; i < 4; i++)
        #pragma unroll
        for (int j = 0; j < 4; j++) acc[i][j] = 0.f;

    int rbase = warp * 16 + (lane >> 2);
    #pragma unroll
    for (int ks = 0; ks < 8; ks++) {
        int kc = ks * 8 + (lane & 3);
        unsigned a[4];
        a[0] = __float_as_uint(As[rbase * PHI_A_STR + kc]);
        a[1] = __float_as_uint(As[(rbase + 8) * PHI_A_STR + kc]);
        a[2] = __float_as_uint(As[rbase * PHI_A_STR + kc + 4]);
        a[3] = __float_as_uint(As[(rbase + 8) * PHI_A_STR + kc + 4]);
        #pragma unroll
        for (int fn = 0; fn < 4; fn++) {
            int cn = fn * 8 + (lane >> 2);
            unsigned b[2];
            b[0] = __float_as_uint(Bs[kc * PHI_B_STR + cn]);
            b[1] = __float_as_uint(Bs[(kc + 4) * PHI_B_STR + cn]);
            mma_tf32(acc[fn], a, b);
        }
    }

    size_t id0 = (size_t)blockIdx.x * 128 + warp * 16 + (lane >> 2);
    size_t id1 = id0 + 8;
    float m0 = (float)mask[id0 / HH];
    float m1 = (float)mask[id1 / HH];
    #pragma unroll
    for (int fn = 0; fn < 4; fn++) {
        int cl = fn * 8 + 2 * (lane & 3);
        *(float2*)(PHK + id0 * FDIM + cl) =
            make_float2(fmaxf(acc[fn][0], 0.f) * m0, fmaxf(acc[fn][1], 0.f) * m0);
        *(float2*)(PHK + id1 * FDIM + cl) =
            make_float2(fmaxf(acc[fn][2], 0.f) * m1, fmaxf(acc[fn][3], 0.f) * m1);
    }
}

// ---------------------------------------------------------------------------
// KV partial reduction: 4 L-chunks per (b,h), deterministic partial buffers
// ---------------------------------------------------------------------------
__global__ __launch_bounds__(256) void kv_part_kernel(
    const float* __restrict__ PHK, const float* __restrict__ V,
    float* __restrict__ KVP, float* __restrict__ KSP)
{
    __shared__ float sph[32 * FDIM];
    __shared__ float sv [32 * HDIM];
    int bh = blockIdx.x;
    int ch = blockIdx.y;
    int b  = bh / HH;
    int h  = bh % HH;
    int tid = threadIdx.x;
    int f  = tid & 31;
    int dg = tid >> 5;
    float acc[8] = {0.f,0.f,0.f,0.f,0.f,0.f,0.f,0.f};
    float sacc = 0.f;

    int rA  = tid >> 3, cA = (tid & 7) * 4;
    int lbeg = ch * (LL / KVCH), lend = lbeg + LL / KVCH;
    for (int l0 = lbeg; l0 < lend; l0 += 32) {
        *(float4*)&sph[rA * FDIM + cA] =
            *(const float4*)(PHK + ((size_t)(b * LL + l0 + rA) * HH + h) * FDIM + cA);
        #pragma unroll
        for (int p = 0; p < 2; p++) {
            int ii = tid + p * 256;
            int rr = ii >> 4, cc = (ii & 15) * 4;
            *(float4*)&sv[rr * HDIM + cc] =
                *(const float4*)(V + (size_t)(b * LL + l0 + rr) * DD + h * HDIM + cc);
        }
        __syncthreads();
        #pragma unroll 8
        for (int r = 0; r < 32; r++) {
            float ph = sph[r * FDIM + f];
            sacc += ph;
            float4 v0 = *(const float4*)&sv[r * HDIM + dg * 8];
            float4 v1 = *(const float4*)&sv[r * HDIM + dg * 8 + 4];
            acc[0] += ph * v0.x; acc[1] += ph * v0.y;
            acc[2] += ph * v0.z; acc[3] += ph * v0.w;
            acc[4] += ph * v1.x; acc[5] += ph * v1.y;
            acc[6] += ph * v1.z; acc[7] += ph * v1.w;
        }
        __syncthreads();
    }
    float* dst = KVP + (((size_t)ch * NBH + bh) * FDIM + f) * HDIM + dg * 8;
    #pragma unroll
    for (int jj = 0; jj < 8; jj++) dst[jj] = acc[jj];
    if (dg == 0) KSP[((size_t)ch * NBH + bh) * FDIM + f] = sacc;
}

__global__ __launch_bounds__(256) void kv_reduce_kernel(
    const float* __restrict__ KVP, const float* __restrict__ KSP,
    float* __restrict__ KV, float* __restrict__ KSUM)
{
    int i = blockIdx.x * 256 + threadIdx.x;
    const int NKV = NBH * FDIM * HDIM;   // 393216
    if (i < NKV) {
        float s = KVP[i] + KVP[NKV + i] + KVP[2 * NKV + i] + KVP[3 * NKV + i];
        KV[i] = s;
    }
    if (i < NBH * FDIM) {
        const int NS = NBH * FDIM;
        KSUM[i] = KSP[i] + KSP[NS + i] + KSP[2 * NS + i] + KSP[3 * NS + i];
    }
}

// ---------------------------------------------------------------------------
// Fused attention output: Y = (relu(rot(Q)@omega) @ KV) * z
// Block = (128 tokens, bh). Two chained tf32 MMAs; PHQ never materialized.
// ---------------------------------------------------------------------------
#define AT_KV_STR 72
#define AT_OFF_PS  (128 * PHI_A_STR)                 // after A
#define AT_OFF_OM  (AT_OFF_PS + 128 * PHI_B_STR)     // after phi
#define AT_OFF_KV  (AT_OFF_OM + HDIM * PHI_B_STR)
#define AT_OFF_DEN (AT_OFF_KV + FDIM * AT_KV_STR)
#define AT_OFF_KSM (AT_OFF_DEN + 128)
#define SMEM_ATT   ((AT_OFF_KSM + FDIM) * 4)          // 75392 bytes

__global__ __launch_bounds__(256, 2) void attn_fused_kernel(
    const float* __restrict__ Q, const float* __restrict__ omega,
    const float* __restrict__ cosT, const float* __restrict__ sinT,
    const float* __restrict__ KV, const float* __restrict__ KSUM,
    float* __restrict__ Y)
{
    extern __shared__ float sm[];
    float* As  = sm;
    float* Ps  = sm + AT_OFF_PS;
    float* Om  = sm + AT_OFF_OM;
    float* Kv  = sm + AT_OFF_KV;
    float* Den = sm + AT_OFF_DEN;
    float* Ksm = sm + AT_OFF_KSM;

    int tid = threadIdx.x, lane = tid & 31, warp = tid >> 5;
    int bh = blockIdx.y;
    int b  = bh / HH, h = bh % HH;
    int tok0 = blockIdx.x * 128;

    // omega -> smem tf32
    {
        int i0 = tid * 8;
        #pragma unroll
        for (int u = 0; u < 2; u++) {
            int i = i0 + u * 4;
            float4 v = *(const float4*)(omega + i);
            int d = i >> 5, f = i & 31;
            Om[d * PHI_B_STR + f + 0] = tf32_rna(v.x);
            Om[d * PHI_B_STR + f + 1] = tf32_rna(v.y);
            Om[d * PHI_B_STR + f + 2] = tf32_rna(v.z);
            Om[d * PHI_B_STR + f + 3] = tf32_rna(v.w);
        }
    }
    // KV tile [32f][64d] -> smem [f][72]
    {
        const float* kvsrc = KV + (size_t)bh * FDIM * HDIM;
        int i0 = tid * 8;
        #pragma unroll
        for (int u = 0; u < 2; u++) {
            int i = i0 + u * 4;
            float4 v = *(const float4*)(kvsrc + i);
            int f = i >> 6, d = i & 63;
            *(float4*)&Kv[f * AT_KV_STR + d] = v;
        }
    }
    if (tid < FDIM) Ksm[tid] = KSUM[bh * FDIM + tid];

    // load Q rows + rotate -> A smem (tf32)
    {
        int row = tid >> 1;
        int j0  = (tid & 1) * 16;
        int l   = tok0 + row;
        const float* xp = Q + ((size_t)(b * LL) + l) * DD + h * HDIM;
        #pragma unroll
        for (int jj = 0; jj < 4; jj++) {
            int j = j0 + jj * 4;
            float4 x1 = *(const float4*)(xp + j);
            float4 x2 = *(const float4*)(xp + j + 32);
            float4 c  = *(const float4*)(cosT + l * 32 + j);
            float4 s  = *(const float4*)(sinT + l * 32 + j);
            float* a1 = As + row * PHI_A_STR + j;
            a1[0]  = tf32_rna(x1.x * c.x - x2.x * s.x);
            a1[32] = tf32_rna(x2.x * c.x + x1.x * s.x);
            a1[1]  = tf32_rna(x1.y * c.y - x2.y * s.y);
            a1[33] = tf32_rna(x2.y * c.y + x1.y * s.y);
            a1[2]  = tf32_rna(x1.z * c.z - x2.z * s.z);
            a1[34] = tf32_rna(x2.z * c.z + x1.z * s.z);
            a1[3]  = tf32_rna(x1.w * c.w - x2.w * s.w);
            a1[35] = tf32_rna(x2.w * c.w + x1.w * s.w);
        }
    }
    __syncthreads();

    int rbase = warp * 16 + (lane >> 2);

    // MMA1: phi = relu( rotQ @ omega )
    {
        float p[4][4];
        #pragma unroll
        for (int i = 0; i < 4; i++)
            #pragma unroll
            for (int j = 0; j < 4; j++) p[i][j] = 0.f;
        #pragma unroll
        for (int ks = 0; ks < 8; ks++) {
            int kc = ks * 8 + (lane & 3);
            unsigned a[4];
            a[0] = __float_as_uint(As[rbase * PHI_A_STR + kc]);
            a[1] = __float_as_uint(As[(rbase + 8) * PHI_A_STR + kc]);
            a[2] = __float_as_uint(As[rbase * PHI_A_STR + kc + 4]);
            a[3] = __float_as_uint(As[(rbase + 8) * PHI_A_STR + kc + 4]);
            #pragma unroll
            for (int fn = 0; fn < 4; fn++) {
                int cn = fn * 8 + (lane >> 2);
                unsigned bb[2];
                bb[0] = __float_as_uint(Om[kc * PHI_B_STR + cn]);
                bb[1] = __float_as_uint(Om[(kc + 4) * PHI_B_STR + cn]);
                mma_tf32(p[fn], a, bb);
            }
        }
        #pragma unroll
        for (int fn = 0; fn < 4; fn++) {
            int cl = fn * 8 + 2 * (lane & 3);
            Ps[rbase * PHI_B_STR + cl]           = fmaxf(p[fn][0], 0.f);
            Ps[rbase * PHI_B_STR + cl + 1]       = fmaxf(p[fn][1], 0.f);
            Ps[(rbase + 8) * PHI_B_STR + cl]     = fmaxf(p[fn][2], 0.f);
            Ps[(rbase + 8) * PHI_B_STR + cl + 1] = fmaxf(p[fn][3], 0.f);
        }
    }
    __syncthreads();

    // den -> z per token
    if (tid < 128) {
        float s = ATTN_EPS;
        #pragma unroll
        for (int f = 0; f < FDIM; f++) s += Ps[tid * PHI_B_STR + f] * Ksm[f];
        Den[tid] = 1.0f / s;
    }
    __syncthreads();

    // MMA2: out = phi @ KV   (B read transposed: B[d][f] = Kv[f][d])
    float o[8][4];
    #pragma unroll
    for (int i = 0; i < 8; i++)
        #pragma unroll
        for (int j = 0; j < 4; j++) o[i][j] = 0.f;
    #pragma unroll
    for (int ks = 0; ks < 4; ks++) {
        int kc = ks * 8 + (lane & 3);
        unsigned a[4];
        a[0] = __float_as_uint(Ps[rbase * PHI_B_STR + kc]);
        a[1] = __float_as_uint(Ps[(rbase + 8) * PHI_B_STR + kc]);
        a[2] = __float_as_uint(Ps[rbase * PHI_B_STR + kc + 4]);
        a[3] = __float_as_uint(Ps[(rbase + 8) * PHI_B_STR + kc + 4]);
        #pragma unroll
        for (int fn = 0; fn < 8; fn++) {
            int cn = fn * 8 + (lane >> 2);
            unsigned bb[2];
            bb[0] = __float_as_uint(Kv[kc * AT_KV_STR + cn]);
            bb[1] = __float_as_uint(Kv[(kc + 4) * AT_KV_STR + cn]);
            mma_tf32(o[fn], a, bb);
        }
    }

    // epilogue: scale by z, write Y
    float z0 = Den[rbase];
    float z1 = Den[rbase + 8];
    size_t t0 = (size_t)(b * LL + tok0) + rbase;
    float* y0 = Y + t0 * DD + h * HDIM;
    float* y1 = Y + (t0 + 8) * DD + h * HDIM;
    #pragma unroll
    for (int fn = 0; fn < 8; fn++) {
        int cl = fn * 8 + 2 * (lane & 3);
        *(float2*)(y0 + cl) = make_float2(o[fn][0] * z0, o[fn][1] * z0);
        *(float2*)(y1 + cl) = make_float2(o[fn][2] * z1, o[fn][3] * z1);
    }
}

// ---------------------------------------------------------------------------
// Warp-per-row LayerNorm: 8 warps/block, 1 row/warp, shuffle-only reduce
// ---------------------------------------------------------------------------
__global__ __launch_bounds__(256) void ln_kernel(
    const float* __restrict__ in, const float* __restrict__ g,
    const float* __restrict__ b, float* __restrict__ out)
{
    int warp = threadIdx.x >> 5, lane = threadIdx.x & 31;
    size_t row = (size_t)blockIdx.x * 8 + warp;
    const float4* ip = (const float4*)(in + row * DD);

    float4 x[6];
    float s = 0.f, s2 = 0.f;
    #pragma unroll
    for (int i = 0; i < 6; i++) {
        x[i] = ip[lane + i * 32];
        s  += x[i].x + x[i].y + x[i].z + x[i].w;
        s2 += x[i].x * x[i].x + x[i].y * x[i].y
            + x[i].z * x[i].z + x[i].w * x[i].w;
    }
    #pragma unroll
    for (int off = 16; off > 0; off >>= 1) {
        s  += __shfl_xor_sync(0xFFFFFFFF, s,  off);
        s2 += __shfl_xor_sync(0xFFFFFFFF, s2, off);
    }
    float mu   = s * (1.0f / DD);
    float rstd = rsqrtf(s2 * (1.0f / DD) - mu * mu + LN_EPS);

    const float4* gp = (const float4*)g;
    const float4* bp = (const float4*)b;
    float4* op = (float4*)(out + row * DD);
    #pragma unroll
    for (int i = 0; i < 6; i++) {
        float4 gg = gp[lane + i * 32];
        float4 bb = bp[lane + i * 32];
        float4 o;
        o.x = (x[i].x - mu) * rstd * gg.x + bb.x;
        o.y = (x[i].y - mu) * rstd * gg.y + bb.y;
        o.z = (x[i].z - mu) * rstd * gg.z + bb.z;
        o.w = (x[i].w - mu) * rstd * gg.w + bb.w;
        op[lane + i * 32] = o;
    }
}

// ---------------------------------------------------------------------------
// Host orchestration
// ---------------------------------------------------------------------------
extern "C" void kernel_launch(void* const* d_in, const int* in_sizes, int n_in,
                              void* d_out, int out_size)
{
    const int*   idx     = (const int*)  d_in[0];
    const int*   mask    = (const int*)  d_in[1];
    const float* tok_emb = (const float*)d_in[2];
    const float* Wq = (const float*)d_in[3];
    const float* bq = (const float*)d_in[4];
    const float* Wk = (const float*)d_in[5];
    const float* bk = (const float*)d_in[6];
    const float* Wv = (const float*)d_in[7];
    const float* bv = (const float*)d_in[8];
    const float* Wo = (const float*)d_in[9];
    const float* bo = (const float*)d_in[10];
    const float* om = (const float*)d_in[11];
    const float* W1 = (const float*)d_in[12];
    const float* b1 = (const float*)d_in[13];
    const float* W2 = (const float*)d_in[14];
    const float* b2 = (const float*)d_in[15];
    const float* g1 = (const float*)d_in[16];
    const float* be1= (const float*)d_in[17];
    const float* g2 = (const float*)d_in[18];
    const float* be2= (const float*)d_in[19];
    const float* gf = (const float*)d_in[20];
    const float* bf = (const float*)d_in[21];
    float* out = (float*)d_out;

    float *X, *Y, *Q, *K, *V, *PHK, *KV, *KSUM, *KVP, *KSP, *COS, *SIN;
    cudaGetSymbolAddress((void**)&X,    g_X);
    cudaGetSymbolAddress((void**)&Y,    g_Y);
    cudaGetSymbolAddress((void**)&Q,    g_Q);
    cudaGetSymbolAddress((void**)&K,    g_K);
    cudaGetSymbolAddress((void**)&V,    g_V);
    cudaGetSymbolAddress((void**)&PHK,  g_PHK);
    cudaGetSymbolAddress((void**)&KV,   g_KV);
    cudaGetSymbolAddress((void**)&KSUM, g_KSUM);
    cudaGetSymbolAddress((void**)&KVP,  g_KVP);
    cudaGetSymbolAddress((void**)&KSP,  g_KSP);
    cudaGetSymbolAddress((void**)&COS,  g_COS);
    cudaGetSymbolAddress((void**)&SIN,  g_SIN);

    cudaFuncSetAttribute(pgemm_kernel,
                         cudaFuncAttributeMaxDynamicSharedMemorySize, SMEM_GEMM);
    cudaFuncSetAttribute(qkv_gemm_kernel,
                         cudaFuncAttributeMaxDynamicSharedMemorySize, SMEM_GEMM);
    cudaFuncSetAttribute(phik_mma_kernel,
                         cudaFuncAttributeMaxDynamicSharedMemorySize, SMEM_PHI);
    cudaFuncSetAttribute(attn_fused_kernel,
                         cudaFuncAttributeMaxDynamicSharedMemorySize, SMEM_ATT);

    const size_t WMAT = (size_t)DD * DD;
    dim3 gGrid(DD / TN, NTOK / TM);       // (6, 256)
    dim3 qkvGrid(3 * DD / TN, NTOK / TM); // (18, 256)
    dim3 attGrid(LL / 128, NBH);          // (16, 192)

    rope_table_kernel<<<(LL * 32) / 256, 256>>>(COS, SIN);
    embed_kernel<<<(NTOK * DD / 4) / 256, 256>>>(idx, tok_emb, X);

    for (int i = 0; i < NLAYER; i++) {
        const float* om_i = om + (size_t)i * HDIM * FDIM;

        qkv_gemm_kernel<<<qkvGrid, 256, SMEM_GEMM>>>(
            X, Wq + i * WMAT, Wk + i * WMAT, Wv + i * WMAT,
            bq + i * DD, bk + i * DD, bv + i * DD, Q, K, V);

        phik_mma_kernel<<<(NTOK * HH) / 128, 256, SMEM_PHI>>>(
            K, om_i, COS, SIN, mask, PHK);

        kv_part_kernel<<<dim3(NBH, KVCH), 256>>>(PHK, V, KVP, KSP);
        kv_reduce_kernel<<<(NBH * FDIM * HDIM) / 256, 256>>>(KVP, KSP, KV, KSUM);

        attn_fused_kernel<<<attGrid, 256, SMEM_ATT>>>(
            Q, om_i, COS, SIN, KV, KSUM, Y);

        // X = Y @ Wo + bo + X
        pgemm_kernel<<<gGrid, 256, SMEM_GEMM>>>(Y, Wo + i * WMAT, bo + i * DD, X, X, 0);
        ln_kernel<<<NTOK / 8, 256>>>(X, g1 + i * DD, be1 + i * DD, X);
        // Q = gelu(X @ W1 + b1)
        pgemm_kernel<<<gGrid, 256, SMEM_GEMM>>>(X, W1 + i * WMAT, b1 + i * DD, nullptr, Q, 1);
        // Y = Q @ W2 + b2 + X
        pgemm_kernel<<<gGrid, 256, SMEM_GEMM>>>(Q, W2 + i * WMAT, b2 + i * DD, X, Y, 0);
        ln_kernel<<<NTOK / 8, 256>>>(Y, g2 + i * DD, be2 + i * DD, X);
    }

    ln_kernel<<<NTOK / 8, 256>>>(X, gf, bf, out);
}